// round 1
// baseline (speedup 1.0000x reference)
#include <cuda_runtime.h>
#include <cstdint>

// Problem constants (capacities; actual sizes read from in_sizes)
#define MAXN 50000
#define DIMD 256      // input feature dim
#define DIMA 128      // per-projection output dim (q or k)
#define QKDIM 256     // q(128) + k(128) per node, contiguous

// Scratch: qk[n][0:128)=q, qk[n][128:256)=k
__device__ float g_qk[(size_t)MAXN * QKDIM];

// ---------------------------------------------------------------------------
// Fused projection GEMM: Y[N,256] = x[N,256] @ W^T + b, W = [Wq; Wk]
// 128x128 block tile, BK=16, 256 threads, 8x8 microtile.
// ---------------------------------------------------------------------------
#define BM 128
#define BN 128
#define BK 16
#define SMPAD 4   // bank-conflict padding

__global__ __launch_bounds__(256, 2)
void gemm_qk_kernel(const float* __restrict__ x,
                    const float* __restrict__ Wq, const float* __restrict__ bq,
                    const float* __restrict__ Wk, const float* __restrict__ bk,
                    float* __restrict__ qk, int N)
{
    __shared__ float As[BK][BM + SMPAD];
    __shared__ float Bs[BK][BN + SMPAD];

    const int tid = threadIdx.x;
    const int block_row = blockIdx.y * BM;
    const int block_col = blockIdx.x * BN;   // 0 or 128

    // microtile coords: 16x16 threads, each 8x8 outputs
    const int tx = tid & 15;    // col group
    const int ty = tid >> 4;    // row group

    // load coords (float4 granularity)
    const int ld_row = tid >> 2;          // 0..63
    const int ld_k4  = (tid & 3) << 2;    // 0,4,8,12

    float acc[8][8];
#pragma unroll
    for (int i = 0; i < 8; i++)
#pragma unroll
        for (int j = 0; j < 8; j++) acc[i][j] = 0.f;

    for (int k0 = 0; k0 < DIMD; k0 += BK) {
        // ---- load A tile (x), transposed into As[k][m] ----
#pragma unroll
        for (int r = 0; r < BM; r += 64) {
            int grow = block_row + ld_row + r;
            int grow_c = grow < N ? grow : (N - 1);   // clamp; store is guarded
            float4 v = *(const float4*)(x + (size_t)grow_c * DIMD + k0 + ld_k4);
            As[ld_k4 + 0][ld_row + r] = v.x;
            As[ld_k4 + 1][ld_row + r] = v.y;
            As[ld_k4 + 2][ld_row + r] = v.z;
            As[ld_k4 + 3][ld_row + r] = v.w;
        }
        // ---- load B tile (weights), Bs[k][j] = W[f][k0+k] ----
#pragma unroll
        for (int r = 0; r < BN; r += 64) {
            int f = block_col + ld_row + r;          // global output feature 0..255
            const float* wrow = (f < DIMA) ? (Wq + (size_t)f * DIMD)
                                           : (Wk + (size_t)(f - DIMA) * DIMD);
            float4 v = *(const float4*)(wrow + k0 + ld_k4);
            Bs[ld_k4 + 0][ld_row + r] = v.x;
            Bs[ld_k4 + 1][ld_row + r] = v.y;
            Bs[ld_k4 + 2][ld_row + r] = v.z;
            Bs[ld_k4 + 3][ld_row + r] = v.w;
        }
        __syncthreads();

#pragma unroll
        for (int kk = 0; kk < BK; kk++) {
            float a[8], b[8];
            *(float4*)&a[0] = *(const float4*)&As[kk][ty * 8];
            *(float4*)&a[4] = *(const float4*)&As[kk][ty * 8 + 4];
            *(float4*)&b[0] = *(const float4*)&Bs[kk][tx * 8];
            *(float4*)&b[4] = *(const float4*)&Bs[kk][tx * 8 + 4];
#pragma unroll
            for (int i = 0; i < 8; i++)
#pragma unroll
                for (int j = 0; j < 8; j++)
                    acc[i][j] = fmaf(a[i], b[j], acc[i][j]);
        }
        __syncthreads();
    }

    // ---- epilogue: add bias, store to qk ----
    float bias[8];
#pragma unroll
    for (int j = 0; j < 8; j++) {
        int f = block_col + tx * 8 + j;
        bias[j] = (f < DIMA) ? bq[f] : bk[f - DIMA];
    }
#pragma unroll
    for (int i = 0; i < 8; i++) {
        int row = block_row + ty * 8 + i;
        if (row < N) {
            float4 v0, v1;
            v0.x = acc[i][0] + bias[0]; v0.y = acc[i][1] + bias[1];
            v0.z = acc[i][2] + bias[2]; v0.w = acc[i][3] + bias[3];
            v1.x = acc[i][4] + bias[4]; v1.y = acc[i][5] + bias[5];
            v1.z = acc[i][6] + bias[6]; v1.w = acc[i][7] + bias[7];
            float* dst = qk + (size_t)row * QKDIM + block_col + tx * 8;
            *(float4*)(dst)     = v0;
            *(float4*)(dst + 4) = v1;
        }
    }
}

// ---------------------------------------------------------------------------
// Zero diagA0 region of output
// ---------------------------------------------------------------------------
__global__ void zero_kernel(float* __restrict__ out, int n)
{
    int i = blockIdx.x * blockDim.x + threadIdx.x;
    if (i < n) out[i] = 0.f;
}

// ---------------------------------------------------------------------------
// Edge kernel: one warp per edge.
//   pre = (dot(q_s,k_d) + dot(q_d,k_s)) / 16 ;  val = exp(pre)
//   diagA1[e] = val ;  atomicAdd into diagA0 at d0[2E+2e], d0[2E+2e+1]
// ---------------------------------------------------------------------------
__global__ __launch_bounds__(256)
void edge_kernel(const float* __restrict__ qk,
                 const int* __restrict__ edge_index,
                 const int* __restrict__ d0_index,
                 float* __restrict__ out,   // [0:N) diagA0, [N:N+E) diagA1
                 int N, int E)
{
    const int gtid = blockIdx.x * blockDim.x + threadIdx.x;
    const int e    = gtid >> 5;
    const int lane = gtid & 31;
    if (e >= E) return;

    const int s = edge_index[e];
    const int d = edge_index[E + e];

    const float4* base_s = (const float4*)(qk + (size_t)s * QKDIM);
    const float4* base_d = (const float4*)(qk + (size_t)d * QKDIM);

    // q at float4 idx [0,32), k at [32,64)
    float4 qs = base_s[lane];
    float4 kd = base_d[lane + 32];
    float4 qd = base_d[lane];
    float4 ks = base_s[lane + 32];

    float acc = qs.x * kd.x + qs.y * kd.y + qs.z * kd.z + qs.w * kd.w
              + qd.x * ks.x + qd.y * ks.y + qd.z * ks.z + qd.w * ks.w;

#pragma unroll
    for (int off = 16; off > 0; off >>= 1)
        acc += __shfl_xor_sync(0xFFFFFFFFu, acc, off);

    if (lane == 0) {
        float val = __expf(acc * (1.0f / 16.0f));
        out[N + e] = val;
        const int n0 = d0_index[2 * E + 2 * e];
        const int n1 = d0_index[2 * E + 2 * e + 1];
        atomicAdd(&out[n0], val);
        atomicAdd(&out[n1], val);
    }
}

// ---------------------------------------------------------------------------
extern "C" void kernel_launch(void* const* d_in, const int* in_sizes, int n_in,
                              void* d_out, int out_size)
{
    const float* x  = (const float*)d_in[0];
    const float* Wq = (const float*)d_in[1];
    const float* bq = (const float*)d_in[2];
    const float* Wk = (const float*)d_in[3];
    const float* bk = (const float*)d_in[4];
    const int* edge_index = (const int*)d_in[5];
    const int* d0_index   = (const int*)d_in[6];
    float* out = (float*)d_out;

    const int N = in_sizes[0] / DIMD;          // 50000
    const int E = in_sizes[5] / 2;             // 800000

    float* qk = nullptr;
    cudaGetSymbolAddress((void**)&qk, g_qk);

    // 1) fused q/k projection
    {
        dim3 grid(QKDIM / BN, (N + BM - 1) / BM);
        gemm_qk_kernel<<<grid, 256>>>(x, Wq, bq, Wk, bk, qk, N);
    }
    // 2) zero diagA0 accumulator region
    zero_kernel<<<(N + 255) / 256, 256>>>(out, N);
    // 3) per-edge score + exp + scatter
    {
        const int warps_per_block = 8;
        int blocks = (E + warps_per_block - 1) / warps_per_block;
        edge_kernel<<<blocks, warps_per_block * 32>>>(qk, edge_index, d0_index,
                                                      out, N, E);
    }
}

// round 2
// speedup vs baseline: 1.5667x; 1.5667x over previous
#include <cuda_runtime.h>
#include <cuda_fp16.h>
#include <cstdint>

#define MAXN 50000
#define DIMD 256      // input feature dim
#define DIMA 128      // q or k output dim
#define QKDIM 256     // q(128) + k(128) per node

// fp16 scratch: qk[n][0:128)=q, qk[n][128:256)=k  (25.6 MB)
__device__ __half g_qkh[(size_t)MAXN * QKDIM];

// ---------------------------------------------------------------------------
// tf32 tensor-core GEMM: Y[N,256] = x @ [Wq;Wk]^T + b, output fp16.
// BM=128, BN=64, BK=16. 256 threads = 8 warps (4 along M x 2 along N),
// each warp 32x32 via m16n8k8 tf32 mma (2 m-tiles x 4 n-tiles x 2 k-steps).
// ---------------------------------------------------------------------------
#define GBM 128
#define GBN 64
#define GBK 16
#define ASTR 20   // smem row stride (uint32): conflict-free for frag loads

__device__ __forceinline__ uint32_t f2tf32(float f) {
    uint32_t r;
    asm("cvt.rna.tf32.f32 %0, %1;" : "=r"(r) : "f"(f));
    return r;
}

__global__ __launch_bounds__(256)
void gemm_qk_tf32_kernel(const float* __restrict__ x,
                         const float* __restrict__ Wq, const float* __restrict__ bq,
                         const float* __restrict__ Wk, const float* __restrict__ bk,
                         __half* __restrict__ qk, int N)
{
    __shared__ uint32_t As[GBM][ASTR];   // [m][k] tf32 bits
    __shared__ uint32_t Bs[GBN][ASTR];   // [n][k] tf32 bits

    const int tid  = threadIdx.x;
    const int lane = tid & 31;
    const int wid  = tid >> 5;
    const int wm   = wid & 3;      // warp row group (32 rows)
    const int wn   = wid >> 2;     // warp col group (32 cols)
    const int gr   = lane >> 2;    // group row 0..7
    const int gc   = lane & 3;     // group col 0..3

    const int br = blockIdx.y * GBM;
    const int bc = blockIdx.x * GBN;   // 0,64,128,192

    // global load coords
    const int a_row0 = tid >> 2;             // 0..63
    const int a_row1 = a_row0 + 64;
    const int a_c4   = (tid & 3) << 2;       // 0,4,8,12
    const int b_row  = tid >> 2;             // 0..63 (feature within block)
    const int b_c4   = (tid & 3) << 2;

    // weight row pointer for this thread's B row
    const int f = bc + b_row;
    const float* wrow = (f < DIMA) ? (Wq + (size_t)f * DIMD)
                                   : (Wk + (size_t)(f - DIMA) * DIMD);

    float acc[2][4][4];
#pragma unroll
    for (int i = 0; i < 2; i++)
#pragma unroll
        for (int j = 0; j < 4; j++)
#pragma unroll
            for (int c = 0; c < 4; c++) acc[i][j][c] = 0.f;

    for (int k0 = 0; k0 < DIMD; k0 += GBK) {
        // prefetch tiles to regs (overlaps with previous iteration's compute)
        int r0 = br + a_row0, r1 = br + a_row1;
        int r0c = r0 < N ? r0 : (N - 1);
        int r1c = r1 < N ? r1 : (N - 1);
        float4 av0 = *(const float4*)(x + (size_t)r0c * DIMD + k0 + a_c4);
        float4 av1 = *(const float4*)(x + (size_t)r1c * DIMD + k0 + a_c4);
        float4 bv  = *(const float4*)(wrow + k0 + b_c4);

        __syncthreads();
        {
            uint4 u;
            u.x = f2tf32(av0.x); u.y = f2tf32(av0.y);
            u.z = f2tf32(av0.z); u.w = f2tf32(av0.w);
            *(uint4*)&As[a_row0][a_c4] = u;
            u.x = f2tf32(av1.x); u.y = f2tf32(av1.y);
            u.z = f2tf32(av1.z); u.w = f2tf32(av1.w);
            *(uint4*)&As[a_row1][a_c4] = u;
            u.x = f2tf32(bv.x);  u.y = f2tf32(bv.y);
            u.z = f2tf32(bv.z);  u.w = f2tf32(bv.w);
            *(uint4*)&Bs[b_row][b_c4] = u;
        }
        __syncthreads();

#pragma unroll
        for (int ks = 0; ks < 2; ks++) {
            const int k8 = ks * 8;
            uint32_t af[2][4];
#pragma unroll
            for (int mt = 0; mt < 2; mt++) {
                const int rb = wm * 32 + mt * 16;
                af[mt][0] = As[rb + gr][k8 + gc];
                af[mt][1] = As[rb + gr + 8][k8 + gc];
                af[mt][2] = As[rb + gr][k8 + gc + 4];
                af[mt][3] = As[rb + gr + 8][k8 + gc + 4];
            }
            uint32_t bf[4][2];
#pragma unroll
            for (int nt = 0; nt < 4; nt++) {
                const int cb = wn * 32 + nt * 8;
                bf[nt][0] = Bs[cb + gr][k8 + gc];
                bf[nt][1] = Bs[cb + gr][k8 + gc + 4];
            }
#pragma unroll
            for (int mt = 0; mt < 2; mt++)
#pragma unroll
                for (int nt = 0; nt < 4; nt++) {
                    asm volatile(
                        "mma.sync.aligned.m16n8k8.row.col.f32.tf32.tf32.f32 "
                        "{%0,%1,%2,%3}, {%4,%5,%6,%7}, {%8,%9}, {%0,%1,%2,%3};\n"
                        : "+f"(acc[mt][nt][0]), "+f"(acc[mt][nt][1]),
                          "+f"(acc[mt][nt][2]), "+f"(acc[mt][nt][3])
                        : "r"(af[mt][0]), "r"(af[mt][1]),
                          "r"(af[mt][2]), "r"(af[mt][3]),
                          "r"(bf[nt][0]), "r"(bf[nt][1]));
                }
        }
    }

    // epilogue: + bias, convert to fp16, store
#pragma unroll
    for (int nt = 0; nt < 4; nt++) {
        const int colg = bc + wn * 32 + nt * 8 + 2 * gc;   // even
        const float b_lo = (colg < DIMA) ? bq[colg]     : bk[colg - DIMA];
        const float b_hi = (colg < DIMA) ? bq[colg + 1] : bk[colg + 1 - DIMA];
#pragma unroll
        for (int mt = 0; mt < 2; mt++) {
            const int row0 = br + wm * 32 + mt * 16 + gr;
            const int row1 = row0 + 8;
            if (row0 < N) {
                __half2 h = __floats2half2_rn(acc[mt][nt][0] + b_lo,
                                              acc[mt][nt][1] + b_hi);
                *(__half2*)(qk + (size_t)row0 * QKDIM + colg) = h;
            }
            if (row1 < N) {
                __half2 h = __floats2half2_rn(acc[mt][nt][2] + b_lo,
                                              acc[mt][nt][3] + b_hi);
                *(__half2*)(qk + (size_t)row1 * QKDIM + colg) = h;
            }
        }
    }
}

// ---------------------------------------------------------------------------
__global__ void zero_kernel(float* __restrict__ out, int n)
{
    int i = blockIdx.x * blockDim.x + threadIdx.x;
    if (i < n) out[i] = 0.f;
}

// ---------------------------------------------------------------------------
// Edge kernel (fp16 gather): one warp per edge, 8 halves per lane per vector.
// ---------------------------------------------------------------------------
__device__ __forceinline__ float h2dot(uint2 a, uint2 b)
{
    float2 a0 = __half22float2(*(const __half2*)&a.x);
    float2 a1 = __half22float2(*(const __half2*)&a.y);
    float2 b0 = __half22float2(*(const __half2*)&b.x);
    float2 b1 = __half22float2(*(const __half2*)&b.y);
    return a0.x * b0.x + a0.y * b0.y + a1.x * b1.x + a1.y * b1.y;
}

__global__ __launch_bounds__(256)
void edge_kernel_h(const __half* __restrict__ qk,
                   const int* __restrict__ edge_index,
                   const int* __restrict__ d0_index,
                   float* __restrict__ out,   // [0:N) diagA0, [N:N+E) diagA1
                   int N, int E)
{
    const int gtid = blockIdx.x * blockDim.x + threadIdx.x;
    const int e    = gtid >> 5;
    const int lane = gtid & 31;
    if (e >= E) return;

    const int s = edge_index[e];
    const int d = edge_index[E + e];

    const uint2* ps = (const uint2*)(qk + (size_t)s * QKDIM);
    const uint2* pd = (const uint2*)(qk + (size_t)d * QKDIM);

    // q at uint2 idx [0,32), k at [32,64)
    uint2 qs = ps[lane];
    uint2 ks = ps[lane + 32];
    uint2 qd = pd[lane];
    uint2 kd = pd[lane + 32];

    float acc = h2dot(qs, kd) + h2dot(qd, ks);

#pragma unroll
    for (int off = 16; off > 0; off >>= 1)
        acc += __shfl_xor_sync(0xFFFFFFFFu, acc, off);

    if (lane == 0) {
        float val = __expf(acc * (1.0f / 16.0f));
        out[N + e] = val;
        const int n0 = d0_index[2 * E + 2 * e];
        const int n1 = d0_index[2 * E + 2 * e + 1];
        atomicAdd(&out[n0], val);
        atomicAdd(&out[n1], val);
    }
}

// ---------------------------------------------------------------------------
extern "C" void kernel_launch(void* const* d_in, const int* in_sizes, int n_in,
                              void* d_out, int out_size)
{
    const float* x  = (const float*)d_in[0];
    const float* Wq = (const float*)d_in[1];
    const float* bq = (const float*)d_in[2];
    const float* Wk = (const float*)d_in[3];
    const float* bk = (const float*)d_in[4];
    const int* edge_index = (const int*)d_in[5];
    const int* d0_index   = (const int*)d_in[6];
    float* out = (float*)d_out;

    const int N = in_sizes[0] / DIMD;          // 50000
    const int E = in_sizes[5] / 2;             // 800000

    __half* qk = nullptr;
    cudaGetSymbolAddress((void**)&qk, g_qkh);

    // 1) fused q/k projection (tf32 tensor cores, fp16 output)
    {
        dim3 grid(QKDIM / GBN, (N + GBM - 1) / GBM);
        gemm_qk_tf32_kernel<<<grid, 256>>>(x, Wq, bq, Wk, bk, qk, N);
    }
    // 2) zero diagA0 accumulator region
    zero_kernel<<<(N + 255) / 256, 256>>>(out, N);
    // 3) per-edge score + exp + scatter
    {
        const int warps_per_block = 8;
        int blocks = (E + warps_per_block - 1) / warps_per_block;
        edge_kernel_h<<<blocks, warps_per_block * 32>>>(qk, edge_index, d0_index,
                                                        out, N, E);
    }
}

// round 3
// speedup vs baseline: 1.7311x; 1.1049x over previous
#include <cuda_runtime.h>
#include <cuda_fp16.h>
#include <cstdint>

#define MAXN 50000
#define DIMD 256      // input feature dim
#define DIMA 128      // q or k output dim
#define QKDIM 256     // q(128) + k(128) per node
#define WROWS 256     // total output features (q+k)

// device scratch
__device__ __half g_qkh[(size_t)MAXN * QKDIM];   // 25.6 MB
__device__ __half g_xh[(size_t)MAXN * DIMD];     // 25.6 MB
__device__ __half g_wh[WROWS * DIMD];            // 128 KB

// ---------------------------------------------------------------------------
// Convert kernels (fp32 -> fp16)
// ---------------------------------------------------------------------------
__global__ void cvt_x_kernel(const float* __restrict__ src,
                             __half* __restrict__ dst, int n4)
{
    int i = blockIdx.x * blockDim.x + threadIdx.x;
    if (i < n4) {
        float4 v = ((const float4*)src)[i];
        __half2 h0 = __floats2half2_rn(v.x, v.y);
        __half2 h1 = __floats2half2_rn(v.z, v.w);
        uint2 u;
        u.x = *(const uint32_t*)&h0;
        u.y = *(const uint32_t*)&h1;
        ((uint2*)dst)[i] = u;
    }
}

__global__ void cvt_w_kernel(const float* __restrict__ Wq,
                             const float* __restrict__ Wk,
                             __half* __restrict__ wh)
{
    int i = blockIdx.x * blockDim.x + threadIdx.x;   // float4 index
    int e = i * 4;
    int row = e >> 8;           // 0..255
    int col = e & 255;
    if (row < WROWS) {
        const float* srow = (row < DIMA) ? (Wq + (size_t)row * DIMD)
                                         : (Wk + (size_t)(row - DIMA) * DIMD);
        float4 v = *(const float4*)(srow + col);
        __half2 h0 = __floats2half2_rn(v.x, v.y);
        __half2 h1 = __floats2half2_rn(v.z, v.w);
        uint2 u;
        u.x = *(const uint32_t*)&h0;
        u.y = *(const uint32_t*)&h1;
        *(uint2*)(wh + (size_t)row * DIMD + col) = u;
    }
}

// ---------------------------------------------------------------------------
// fp16 tensor-core GEMM: qk[N,256] = xh @ wh^T + b  (fp32 accum, fp16 out)
// BM=128, BN=64, BK=64, 256 threads (8 warps: 4 along M x 2 along N).
// cp.async double-buffered smem, 8-way swizzle (128B rows), ldmatrix.x4.
// ---------------------------------------------------------------------------
#define BM 128
#define BN 64
#define BK 64

__device__ __forceinline__ void cp16(uint32_t dst, const void* src) {
    asm volatile("cp.async.cg.shared.global [%0], [%1], 16;\n"
                 :: "r"(dst), "l"(src));
}
__device__ __forceinline__ void cp_commit() {
    asm volatile("cp.async.commit_group;\n");
}
__device__ __forceinline__ void ldsm_x4(uint32_t* r, uint32_t addr) {
    asm volatile("ldmatrix.sync.aligned.m8n8.x4.shared.b16 {%0,%1,%2,%3}, [%4];"
                 : "=r"(r[0]), "=r"(r[1]), "=r"(r[2]), "=r"(r[3]) : "r"(addr));
}

__global__ __launch_bounds__(256)
void gemm_qk_h_kernel(const __half* __restrict__ xh, const __half* __restrict__ wh,
                      const float* __restrict__ bq, const float* __restrict__ bk,
                      __half* __restrict__ qk, int N)
{
    __shared__ __half As[2][BM * BK];   // swizzled [m][k]
    __shared__ __half Bs[2][BN * BK];   // swizzled [n][k]

    const int tid  = threadIdx.x;
    const int lane = tid & 31;
    const int wid  = tid >> 5;
    const int wm   = wid & 3;      // 32-row group
    const int wn   = wid >> 2;     // 32-col group
    const int gr   = lane >> 2;
    const int gc   = lane & 3;

    const int br = blockIdx.y * BM;
    const int bc = blockIdx.x * BN;    // 0,64,128,192

    const uint32_t as0 = (uint32_t)__cvta_generic_to_shared(&As[0][0]);
    const uint32_t as1 = (uint32_t)__cvta_generic_to_shared(&As[1][0]);
    const uint32_t bs0 = (uint32_t)__cvta_generic_to_shared(&Bs[0][0]);
    const uint32_t bs1 = (uint32_t)__cvta_generic_to_shared(&Bs[1][0]);

    // ldmatrix per-lane descriptors
    const int rA  = wm * 32 + (lane & 15);     // A row within block tile
    const int kcA = lane >> 4;                 // 0/1 : k-chunk offset
    const int swA = rA & 7;
    const int nB  = wn * 32 + ((lane >> 4) << 3) + (lane & 7);
    const int kcB = (lane >> 3) & 1;
    const int swB = nB & 7;

    float acc[2][4][4];
#pragma unroll
    for (int i = 0; i < 2; i++)
#pragma unroll
        for (int j = 0; j < 4; j++)
#pragma unroll
            for (int c = 0; c < 4; c++) acc[i][j][c] = 0.f;

    // ---- cp.async stage issue ----
    auto issue = [&](int buf, int k0) {
        uint32_t ab = buf ? as1 : as0;
        uint32_t bb = buf ? bs1 : bs0;
#pragma unroll
        for (int i = 0; i < 4; i++) {                  // A: 1024 chunks
            int cid = tid + i * 256;
            int row = cid >> 3, c = cid & 7;
            int grow = br + row; if (grow >= N) grow = N - 1;
            uint32_t dst = ab + (uint32_t)(row * 64 + ((c ^ (row & 7)) << 3)) * 2;
            cp16(dst, xh + (size_t)grow * DIMD + k0 + c * 8);
        }
#pragma unroll
        for (int i = 0; i < 2; i++) {                  // B: 512 chunks
            int cid = tid + i * 256;
            int row = cid >> 3, c = cid & 7;
            uint32_t dst = bb + (uint32_t)(row * 64 + ((c ^ (row & 7)) << 3)) * 2;
            cp16(dst, wh + (size_t)(bc + row) * DIMD + k0 + c * 8);
        }
        cp_commit();
    };

    auto compute = [&](int buf) {
        uint32_t ab = buf ? as1 : as0;
        uint32_t bb = buf ? bs1 : bs0;
#pragma unroll
        for (int kk = 0; kk < 4; kk++) {
            uint32_t a[2][4], b[2][4];
#pragma unroll
            for (int mt = 0; mt < 2; mt++) {
                int hidx = (rA + mt * 16) * 64 + (((kk * 2 + kcA) ^ swA) << 3);
                ldsm_x4(a[mt], ab + (uint32_t)hidx * 2);
            }
#pragma unroll
            for (int np = 0; np < 2; np++) {
                int hidx = (nB + np * 16) * 64 + (((kk * 2 + kcB) ^ swB) << 3);
                ldsm_x4(b[np], bb + (uint32_t)hidx * 2);
            }
#pragma unroll
            for (int mt = 0; mt < 2; mt++)
#pragma unroll
                for (int np = 0; np < 2; np++)
#pragma unroll
                    for (int q = 0; q < 2; q++) {
                        float* c = acc[mt][np * 2 + q];
                        asm volatile(
                            "mma.sync.aligned.m16n8k16.row.col.f32.f16.f16.f32 "
                            "{%0,%1,%2,%3}, {%4,%5,%6,%7}, {%8,%9}, {%0,%1,%2,%3};\n"
                            : "+f"(c[0]), "+f"(c[1]), "+f"(c[2]), "+f"(c[3])
                            : "r"(a[mt][0]), "r"(a[mt][1]),
                              "r"(a[mt][2]), "r"(a[mt][3]),
                              "r"(b[np][q * 2]), "r"(b[np][q * 2 + 1]));
                    }
        }
    };

    issue(0, 0);
#pragma unroll
    for (int s = 0; s < 4; s++) {
        if (s + 1 < 4) {
            issue((s + 1) & 1, (s + 1) * BK);
            asm volatile("cp.async.wait_group 1;\n");
        } else {
            asm volatile("cp.async.wait_group 0;\n");
        }
        __syncthreads();
        compute(s & 1);
        __syncthreads();
    }

    // ---- epilogue: + bias, fp16 store ----
#pragma unroll
    for (int nt = 0; nt < 4; nt++) {
        const int colg = bc + wn * 32 + nt * 8 + 2 * gc;
        const float b_lo = (colg < DIMA) ? bq[colg]     : bk[colg - DIMA];
        const float b_hi = (colg < DIMA) ? bq[colg + 1] : bk[colg + 1 - DIMA];
#pragma unroll
        for (int mt = 0; mt < 2; mt++) {
            const int row0 = br + wm * 32 + mt * 16 + gr;
            const int row1 = row0 + 8;
            if (row0 < N) {
                __half2 h = __floats2half2_rn(acc[mt][nt][0] + b_lo,
                                              acc[mt][nt][1] + b_hi);
                *(__half2*)(qk + (size_t)row0 * QKDIM + colg) = h;
            }
            if (row1 < N) {
                __half2 h = __floats2half2_rn(acc[mt][nt][2] + b_lo,
                                              acc[mt][nt][3] + b_hi);
                *(__half2*)(qk + (size_t)row1 * QKDIM + colg) = h;
            }
        }
    }
}

// ---------------------------------------------------------------------------
__global__ void zero_kernel(float* __restrict__ out, int n)
{
    int i = blockIdx.x * blockDim.x + threadIdx.x;
    if (i < n) out[i] = 0.f;
}

// ---------------------------------------------------------------------------
// Edge kernel: warp/edge, full-row uint4 loads + butterfly half-swap.
// ---------------------------------------------------------------------------
__device__ __forceinline__ float dot8h(uint4 a, uint4 b)
{
    const __half2* pa = (const __half2*)&a;
    const __half2* pb = (const __half2*)&b;
    float s = 0.f;
#pragma unroll
    for (int i = 0; i < 4; i++) {
        float2 fa = __half22float2(pa[i]);
        float2 fb = __half22float2(pb[i]);
        s += fa.x * fb.x + fa.y * fb.y;
    }
    return s;
}

__global__ __launch_bounds__(256)
void edge_kernel_h(const __half* __restrict__ qk,
                   const int* __restrict__ edge_index,
                   const int* __restrict__ d0_index,
                   float* __restrict__ out,   // [0:N) diagA0, [N:N+E) diagA1
                   int N, int E)
{
    const int gtid = blockIdx.x * blockDim.x + threadIdx.x;
    const int e    = gtid >> 5;
    const int lane = gtid & 31;
    if (e >= E) return;

    const int s = edge_index[e];
    const int d = edge_index[E + e];

    // whole 512B row: lanes 0-15 hold q chunks, 16-31 hold k chunks
    uint4 vs = ((const uint4*)(qk + (size_t)s * QKDIM))[lane];
    uint4 vd = ((const uint4*)(qk + (size_t)d * QKDIM))[lane];

    // swap q<->k halves of the d row across the warp
    uint4 wd;
    wd.x = __shfl_xor_sync(0xFFFFFFFFu, vd.x, 16);
    wd.y = __shfl_xor_sync(0xFFFFFFFFu, vd.y, 16);
    wd.z = __shfl_xor_sync(0xFFFFFFFFu, vd.z, 16);
    wd.w = __shfl_xor_sync(0xFFFFFFFFu, vd.w, 16);

    // lanes 0-15: q_s . k_d ; lanes 16-31: k_s . q_d
    float acc = dot8h(vs, wd);

#pragma unroll
    for (int off = 16; off > 0; off >>= 1)
        acc += __shfl_xor_sync(0xFFFFFFFFu, acc, off);

    if (lane < 2) {
        float val = __expf(acc * (1.0f / 16.0f));
        if (lane == 0) {
            out[N + e] = val;
            atomicAdd(&out[d0_index[2 * E + 2 * e]], val);
        } else {
            atomicAdd(&out[d0_index[2 * E + 2 * e + 1]], val);
        }
    }
}

// ---------------------------------------------------------------------------
extern "C" void kernel_launch(void* const* d_in, const int* in_sizes, int n_in,
                              void* d_out, int out_size)
{
    const float* x  = (const float*)d_in[0];
    const float* Wq = (const float*)d_in[1];
    const float* bq = (const float*)d_in[2];
    const float* Wk = (const float*)d_in[3];
    const float* bk = (const float*)d_in[4];
    const int* edge_index = (const int*)d_in[5];
    const int* d0_index   = (const int*)d_in[6];
    float* out = (float*)d_out;

    const int N = in_sizes[0] / DIMD;          // 50000
    const int E = in_sizes[5] / 2;             // 800000

    __half *qk, *xh, *wh;
    cudaGetSymbolAddress((void**)&qk, g_qkh);
    cudaGetSymbolAddress((void**)&xh, g_xh);
    cudaGetSymbolAddress((void**)&wh, g_wh);

    // 0) fp32 -> fp16 converts
    {
        int n4 = (N * DIMD) / 4;
        cvt_x_kernel<<<(n4 + 255) / 256, 256>>>(x, xh, n4);
        cvt_w_kernel<<<(WROWS * DIMD / 4 + 255) / 256, 256>>>(Wq, Wk, wh);
    }
    // 1) fused q/k projection (fp16 tensor cores)
    {
        dim3 grid(WROWS / BN, (N + BM - 1) / BM);
        gemm_qk_h_kernel<<<grid, 256>>>(xh, wh, bq, bk, qk, N);
    }
    // 2) zero diagA0 accumulator region
    zero_kernel<<<(N + 255) / 256, 256>>>(out, N);
    // 3) per-edge score + exp + scatter
    {
        int blocks = (E + 7) / 8;
        edge_kernel_h<<<blocks, 256>>>(qk, edge_index, d0_index, out, N, E);
    }
}

// round 4
// speedup vs baseline: 1.8294x; 1.0568x over previous
#include <cuda_runtime.h>
#include <cuda_fp16.h>
#include <cstdint>

#define MAXN 50000
#define DIMD 256      // input feature dim
#define DIMA 128      // q or k output dim
#define QKDIM 256     // q(128) + k(128) per node
#define WROWS 256     // total output features (q+k)

// device scratch
__device__ __half g_qkh[(size_t)MAXN * QKDIM];   // 25.6 MB
__device__ __half g_xh[(size_t)MAXN * DIMD];     // 25.6 MB
__device__ __half g_wh[WROWS * DIMD];            // 128 KB

// ---------------------------------------------------------------------------
// Convert kernels (fp32 -> fp16); cvt_x also zeroes out[0:N) (diagA0 accum).
// ---------------------------------------------------------------------------
__global__ void cvt_x_kernel(const float* __restrict__ src,
                             __half* __restrict__ dst,
                             float* __restrict__ out, int n4, int N)
{
    int i = blockIdx.x * blockDim.x + threadIdx.x;
    if (i < n4) {
        float4 v = ((const float4*)src)[i];
        __half2 h0 = __floats2half2_rn(v.x, v.y);
        __half2 h1 = __floats2half2_rn(v.z, v.w);
        uint2 u;
        u.x = *(const uint32_t*)&h0;
        u.y = *(const uint32_t*)&h1;
        ((uint2*)dst)[i] = u;
    }
    if (i < N) out[i] = 0.f;
}

__global__ void cvt_w_kernel(const float* __restrict__ Wq,
                             const float* __restrict__ Wk,
                             __half* __restrict__ wh)
{
    int i = blockIdx.x * blockDim.x + threadIdx.x;   // float4 index
    int e = i * 4;
    int row = e >> 8;           // 0..255
    int col = e & 255;
    if (row < WROWS) {
        const float* srow = (row < DIMA) ? (Wq + (size_t)row * DIMD)
                                         : (Wk + (size_t)(row - DIMA) * DIMD);
        float4 v = *(const float4*)(srow + col);
        __half2 h0 = __floats2half2_rn(v.x, v.y);
        __half2 h1 = __floats2half2_rn(v.z, v.w);
        uint2 u;
        u.x = *(const uint32_t*)&h0;
        u.y = *(const uint32_t*)&h1;
        *(uint2*)(wh + (size_t)row * DIMD + col) = u;
    }
}

// ---------------------------------------------------------------------------
// fp16 tensor-core GEMM: qk[N,256] = xh @ wh^T + b  (fp32 accum, fp16 out)
// BM=64, BN=128, BK=64, 256 threads (8 warps: 2 along M x 4 along N).
// cp.async double-buffered smem, 8-way swizzle (128B rows), ldmatrix.x4.
// ---------------------------------------------------------------------------
#define BM 64
#define BN 128
#define BK 64

__device__ __forceinline__ void cp16(uint32_t dst, const void* src) {
    asm volatile("cp.async.cg.shared.global [%0], [%1], 16;\n"
                 :: "r"(dst), "l"(src));
}
__device__ __forceinline__ void cp_commit() {
    asm volatile("cp.async.commit_group;\n");
}
__device__ __forceinline__ void ldsm_x4(uint32_t* r, uint32_t addr) {
    asm volatile("ldmatrix.sync.aligned.m8n8.x4.shared.b16 {%0,%1,%2,%3}, [%4];"
                 : "=r"(r[0]), "=r"(r[1]), "=r"(r[2]), "=r"(r[3]) : "r"(addr));
}

__global__ __launch_bounds__(256)
void gemm_qk_h_kernel(const __half* __restrict__ xh, const __half* __restrict__ wh,
                      const float* __restrict__ bq, const float* __restrict__ bk,
                      __half* __restrict__ qk, int N)
{
    __shared__ __half As[2][BM * BK];   // swizzled [m][k]
    __shared__ __half Bs[2][BN * BK];   // swizzled [n][k]

    const int tid  = threadIdx.x;
    const int lane = tid & 31;
    const int wid  = tid >> 5;
    const int wm   = wid & 1;      // 2 x 32-row groups
    const int wn   = wid >> 1;     // 4 x 32-col groups
    const int gr   = lane >> 2;
    const int gc   = lane & 3;

    const int br = blockIdx.y * BM;
    const int bc = blockIdx.x * BN;    // 0,128

    const uint32_t as0 = (uint32_t)__cvta_generic_to_shared(&As[0][0]);
    const uint32_t as1 = (uint32_t)__cvta_generic_to_shared(&As[1][0]);
    const uint32_t bs0 = (uint32_t)__cvta_generic_to_shared(&Bs[0][0]);
    const uint32_t bs1 = (uint32_t)__cvta_generic_to_shared(&Bs[1][0]);

    // ldmatrix per-lane descriptors
    const int rA  = wm * 32 + (lane & 15);     // A row within block tile
    const int kcA = lane >> 4;                 // 0/1 : k-chunk offset
    const int swA = rA & 7;
    const int nB  = wn * 32 + ((lane >> 4) << 3) + (lane & 7);
    const int kcB = (lane >> 3) & 1;
    const int swB = nB & 7;

    float acc[2][4][4];
#pragma unroll
    for (int i = 0; i < 2; i++)
#pragma unroll
        for (int j = 0; j < 4; j++)
#pragma unroll
            for (int c = 0; c < 4; c++) acc[i][j][c] = 0.f;

    // ---- cp.async stage issue ----
    auto issue = [&](int buf, int k0) {
        uint32_t ab = buf ? as1 : as0;
        uint32_t bb = buf ? bs1 : bs0;
#pragma unroll
        for (int i = 0; i < 2; i++) {                  // A: 512 chunks
            int cid = tid + i * 256;
            int row = cid >> 3, c = cid & 7;
            int grow = br + row; if (grow >= N) grow = N - 1;
            uint32_t dst = ab + (uint32_t)(row * 64 + ((c ^ (row & 7)) << 3)) * 2;
            cp16(dst, xh + (size_t)grow * DIMD + k0 + c * 8);
        }
#pragma unroll
        for (int i = 0; i < 4; i++) {                  // B: 1024 chunks
            int cid = tid + i * 256;
            int row = cid >> 3, c = cid & 7;
            uint32_t dst = bb + (uint32_t)(row * 64 + ((c ^ (row & 7)) << 3)) * 2;
            cp16(dst, wh + (size_t)(bc + row) * DIMD + k0 + c * 8);
        }
        cp_commit();
    };

    auto compute = [&](int buf) {
        uint32_t ab = buf ? as1 : as0;
        uint32_t bb = buf ? bs1 : bs0;
#pragma unroll
        for (int kk = 0; kk < 4; kk++) {
            uint32_t a[2][4], b[2][4];
#pragma unroll
            for (int mt = 0; mt < 2; mt++) {
                int hidx = (rA + mt * 16) * 64 + (((kk * 2 + kcA) ^ swA) << 3);
                ldsm_x4(a[mt], ab + (uint32_t)hidx * 2);
            }
#pragma unroll
            for (int np = 0; np < 2; np++) {
                int hidx = (nB + np * 16) * 64 + (((kk * 2 + kcB) ^ swB) << 3);
                ldsm_x4(b[np], bb + (uint32_t)hidx * 2);
            }
#pragma unroll
            for (int mt = 0; mt < 2; mt++)
#pragma unroll
                for (int np = 0; np < 2; np++)
#pragma unroll
                    for (int q = 0; q < 2; q++) {
                        float* c = acc[mt][np * 2 + q];
                        asm volatile(
                            "mma.sync.aligned.m16n8k16.row.col.f32.f16.f16.f32 "
                            "{%0,%1,%2,%3}, {%4,%5,%6,%7}, {%8,%9}, {%0,%1,%2,%3};\n"
                            : "+f"(c[0]), "+f"(c[1]), "+f"(c[2]), "+f"(c[3])
                            : "r"(a[mt][0]), "r"(a[mt][1]),
                              "r"(a[mt][2]), "r"(a[mt][3]),
                              "r"(b[np][q * 2]), "r"(b[np][q * 2 + 1]));
                    }
        }
    };

    issue(0, 0);
#pragma unroll
    for (int s = 0; s < 4; s++) {
        if (s + 1 < 4) {
            issue((s + 1) & 1, (s + 1) * BK);
            asm volatile("cp.async.wait_group 1;\n");
        } else {
            asm volatile("cp.async.wait_group 0;\n");
        }
        __syncthreads();
        compute(s & 1);
        __syncthreads();
    }

    // ---- epilogue: + bias, fp16 store ----
#pragma unroll
    for (int nt = 0; nt < 4; nt++) {
        const int colg = bc + wn * 32 + nt * 8 + 2 * gc;
        const float b_lo = (colg < DIMA) ? bq[colg]     : bk[colg - DIMA];
        const float b_hi = (colg < DIMA) ? bq[colg + 1] : bk[colg + 1 - DIMA];
#pragma unroll
        for (int mt = 0; mt < 2; mt++) {
            const int row0 = br + wm * 32 + mt * 16 + gr;
            const int row1 = row0 + 8;
            if (row0 < N) {
                __half2 h = __floats2half2_rn(acc[mt][nt][0] + b_lo,
                                              acc[mt][nt][1] + b_hi);
                *(__half2*)(qk + (size_t)row0 * QKDIM + colg) = h;
            }
            if (row1 < N) {
                __half2 h = __floats2half2_rn(acc[mt][nt][2] + b_lo,
                                              acc[mt][nt][3] + b_hi);
                *(__half2*)(qk + (size_t)row1 * QKDIM + colg) = h;
            }
        }
    }
}

// ---------------------------------------------------------------------------
// Edge kernel: warp/edge. Lane i loads src chunk i and dst chunk i^16 —
// the q/k halves line up without any shuffle. hfma2 partial dot.
// ---------------------------------------------------------------------------
__global__ __launch_bounds__(256)
void edge_kernel_h(const __half* __restrict__ qk,
                   const int* __restrict__ edge_index,
                   const int* __restrict__ d0_index,
                   float* __restrict__ out,   // [0:N) diagA0, [N:N+E) diagA1
                   int N, int E)
{
    const int gtid = blockIdx.x * blockDim.x + threadIdx.x;
    const int e    = gtid >> 5;
    const int lane = gtid & 31;
    if (e >= E) return;

    const int s = edge_index[e];
    const int d = edge_index[E + e];

    uint4 vs = ((const uint4*)(qk + (size_t)s * QKDIM))[lane];
    uint4 vd = ((const uint4*)(qk + (size_t)d * QKDIM))[lane ^ 16];

    // lanes 0-15: q_s . k_d partials; lanes 16-31: k_s . q_d partials
    const __half2* pa = (const __half2*)&vs;
    const __half2* pb = (const __half2*)&vd;
    __half2 h = __hmul2(pa[0], pb[0]);
    h = __hfma2(pa[1], pb[1], h);
    h = __hfma2(pa[2], pb[2], h);
    h = __hfma2(pa[3], pb[3], h);
    float2 f = __half22float2(h);
    float acc = f.x + f.y;

#pragma unroll
    for (int off = 16; off > 0; off >>= 1)
        acc += __shfl_xor_sync(0xFFFFFFFFu, acc, off);

    if (lane < 2) {
        float val = __expf(acc * (1.0f / 16.0f));
        if (lane == 0) {
            out[N + e] = val;
            atomicAdd(&out[d0_index[2 * E + 2 * e]], val);
        } else {
            atomicAdd(&out[d0_index[2 * E + 2 * e + 1]], val);
        }
    }
}

// ---------------------------------------------------------------------------
extern "C" void kernel_launch(void* const* d_in, const int* in_sizes, int n_in,
                              void* d_out, int out_size)
{
    const float* x  = (const float*)d_in[0];
    const float* Wq = (const float*)d_in[1];
    const float* bq = (const float*)d_in[2];
    const float* Wk = (const float*)d_in[3];
    const float* bk = (const float*)d_in[4];
    const int* edge_index = (const int*)d_in[5];
    const int* d0_index   = (const int*)d_in[6];
    float* out = (float*)d_out;

    const int N = in_sizes[0] / DIMD;          // 50000
    const int E = in_sizes[5] / 2;             // 800000

    __half *qk, *xh, *wh;
    cudaGetSymbolAddress((void**)&qk, g_qkh);
    cudaGetSymbolAddress((void**)&xh, g_xh);
    cudaGetSymbolAddress((void**)&wh, g_wh);

    // 0) fp32 -> fp16 converts (+ zero diagA0 region)
    {
        int n4 = (N * DIMD) / 4;
        cvt_x_kernel<<<(n4 + 255) / 256, 256>>>(x, xh, out, n4, N);
        cvt_w_kernel<<<(WROWS * DIMD / 4 + 255) / 256, 256>>>(Wq, Wk, wh);
    }
    // 1) fused q/k projection (fp16 tensor cores)
    {
        dim3 grid(WROWS / BN, (N + BM - 1) / BM);
        gemm_qk_h_kernel<<<grid, 256>>>(xh, wh, bq, bk, qk, N);
    }
    // 2) per-edge score + exp + scatter
    {
        int blocks = (E + 7) / 8;
        edge_kernel_h<<<blocks, 256>>>(qk, edge_index, d0_index, out, N, E);
    }
}

// round 5
// speedup vs baseline: 3.1215x; 1.7063x over previous
#include <cuda_runtime.h>
#include <cuda_fp16.h>
#include <cstdint>

#define MAXN 50000
#define DIMD 256      // input feature dim
#define DIMA 128      // q or k output dim
#define QKDIM 256     // q(128) + k(128) per node
#define WROWS 256     // total output features (q+k)

// device scratch
__device__ __half g_qkh[(size_t)MAXN * QKDIM];   // 25.6 MB
__device__ __half g_xh[(size_t)MAXN * DIMD];     // 25.6 MB
__device__ __half g_wh[WROWS * DIMD];            // 128 KB

// ---------------------------------------------------------------------------
// Convert kernels (fp32 -> fp16); cvt_x also zeroes out[0:N) (diagA0 accum).
// ---------------------------------------------------------------------------
__global__ void cvt_x_kernel(const float* __restrict__ src,
                             __half* __restrict__ dst,
                             float* __restrict__ out, int n4, int N)
{
    int i = blockIdx.x * blockDim.x + threadIdx.x;
    if (i < n4) {
        float4 v = ((const float4*)src)[i];
        __half2 h0 = __floats2half2_rn(v.x, v.y);
        __half2 h1 = __floats2half2_rn(v.z, v.w);
        uint2 u;
        u.x = *(const uint32_t*)&h0;
        u.y = *(const uint32_t*)&h1;
        ((uint2*)dst)[i] = u;
    }
    if (i < N) out[i] = 0.f;
}

__global__ void cvt_w_kernel(const float* __restrict__ Wq,
                             const float* __restrict__ Wk,
                             __half* __restrict__ wh)
{
    int i = blockIdx.x * blockDim.x + threadIdx.x;   // float4 index
    int e = i * 4;
    int row = e >> 8;           // 0..255
    int col = e & 255;
    if (row < WROWS) {
        const float* srow = (row < DIMA) ? (Wq + (size_t)row * DIMD)
                                         : (Wk + (size_t)(row - DIMA) * DIMD);
        float4 v = *(const float4*)(srow + col);
        __half2 h0 = __floats2half2_rn(v.x, v.y);
        __half2 h1 = __floats2half2_rn(v.z, v.w);
        uint2 u;
        u.x = *(const uint32_t*)&h0;
        u.y = *(const uint32_t*)&h1;
        *(uint2*)(wh + (size_t)row * DIMD + col) = u;
    }
}

// ---------------------------------------------------------------------------
// fp16 tensor-core GEMM: qk[N,256] = xh @ wh^T + b  (fp32 accum, fp16 out)
// BM=64, BN=128, BK=64, 256 threads (8 warps: 2 along M x 4 along N).
// cp.async double-buffered smem, 8-way swizzle (128B rows), ldmatrix.x4.
// ---------------------------------------------------------------------------
#define BM 64
#define BN 128
#define BK 64

__device__ __forceinline__ void cp16(uint32_t dst, const void* src) {
    asm volatile("cp.async.cg.shared.global [%0], [%1], 16;\n"
                 :: "r"(dst), "l"(src));
}
__device__ __forceinline__ void cp_commit() {
    asm volatile("cp.async.commit_group;\n");
}
__device__ __forceinline__ void ldsm_x4(uint32_t* r, uint32_t addr) {
    asm volatile("ldmatrix.sync.aligned.m8n8.x4.shared.b16 {%0,%1,%2,%3}, [%4];"
                 : "=r"(r[0]), "=r"(r[1]), "=r"(r[2]), "=r"(r[3]) : "r"(addr));
}

__global__ __launch_bounds__(256)
void gemm_qk_h_kernel(const __half* __restrict__ xh, const __half* __restrict__ wh,
                      const float* __restrict__ bq, const float* __restrict__ bk,
                      __half* __restrict__ qk, int N)
{
    __shared__ __half As[2][BM * BK];   // swizzled [m][k]
    __shared__ __half Bs[2][BN * BK];   // swizzled [n][k]

    const int tid  = threadIdx.x;
    const int lane = tid & 31;
    const int wid  = tid >> 5;
    const int wm   = wid & 1;      // 2 x 32-row groups
    const int wn   = wid >> 1;     // 4 x 32-col groups
    const int gr   = lane >> 2;
    const int gc   = lane & 3;

    const int br = blockIdx.y * BM;
    const int bc = blockIdx.x * BN;    // 0,128

    const uint32_t as0 = (uint32_t)__cvta_generic_to_shared(&As[0][0]);
    const uint32_t as1 = (uint32_t)__cvta_generic_to_shared(&As[1][0]);
    const uint32_t bs0 = (uint32_t)__cvta_generic_to_shared(&Bs[0][0]);
    const uint32_t bs1 = (uint32_t)__cvta_generic_to_shared(&Bs[1][0]);

    // ldmatrix per-lane descriptors
    const int rA  = wm * 32 + (lane & 15);     // A row within block tile
    const int kcA = lane >> 4;                 // 0/1 : k-chunk offset
    const int swA = rA & 7;
    const int nB  = wn * 32 + ((lane >> 4) << 3) + (lane & 7);
    const int kcB = (lane >> 3) & 1;
    const int swB = nB & 7;

    float acc[2][4][4];
#pragma unroll
    for (int i = 0; i < 2; i++)
#pragma unroll
        for (int j = 0; j < 4; j++)
#pragma unroll
            for (int c = 0; c < 4; c++) acc[i][j][c] = 0.f;

    // ---- cp.async stage issue ----
    auto issue = [&](int buf, int k0) {
        uint32_t ab = buf ? as1 : as0;
        uint32_t bb = buf ? bs1 : bs0;
#pragma unroll
        for (int i = 0; i < 2; i++) {                  // A: 512 chunks
            int cid = tid + i * 256;
            int row = cid >> 3, c = cid & 7;
            int grow = br + row; if (grow >= N) grow = N - 1;
            uint32_t dst = ab + (uint32_t)(row * 64 + ((c ^ (row & 7)) << 3)) * 2;
            cp16(dst, xh + (size_t)grow * DIMD + k0 + c * 8);
        }
#pragma unroll
        for (int i = 0; i < 4; i++) {                  // B: 1024 chunks
            int cid = tid + i * 256;
            int row = cid >> 3, c = cid & 7;
            uint32_t dst = bb + (uint32_t)(row * 64 + ((c ^ (row & 7)) << 3)) * 2;
            cp16(dst, wh + (size_t)(bc + row) * DIMD + k0 + c * 8);
        }
        cp_commit();
    };

    auto compute = [&](int buf) {
        uint32_t ab = buf ? as1 : as0;
        uint32_t bb = buf ? bs1 : bs0;
#pragma unroll
        for (int kk = 0; kk < 4; kk++) {
            uint32_t a[2][4], b[2][4];
#pragma unroll
            for (int mt = 0; mt < 2; mt++) {
                int hidx = (rA + mt * 16) * 64 + (((kk * 2 + kcA) ^ swA) << 3);
                ldsm_x4(a[mt], ab + (uint32_t)hidx * 2);
            }
#pragma unroll
            for (int np = 0; np < 2; np++) {
                int hidx = (nB + np * 16) * 64 + (((kk * 2 + kcB) ^ swB) << 3);
                ldsm_x4(b[np], bb + (uint32_t)hidx * 2);
            }
#pragma unroll
            for (int mt = 0; mt < 2; mt++)
#pragma unroll
                for (int np = 0; np < 2; np++)
#pragma unroll
                    for (int q = 0; q < 2; q++) {
                        float* c = acc[mt][np * 2 + q];
                        asm volatile(
                            "mma.sync.aligned.m16n8k16.row.col.f32.f16.f16.f32 "
                            "{%0,%1,%2,%3}, {%4,%5,%6,%7}, {%8,%9}, {%0,%1,%2,%3};\n"
                            : "+f"(c[0]), "+f"(c[1]), "+f"(c[2]), "+f"(c[3])
                            : "r"(a[mt][0]), "r"(a[mt][1]),
                              "r"(a[mt][2]), "r"(a[mt][3]),
                              "r"(b[np][q * 2]), "r"(b[np][q * 2 + 1]));
                    }
        }
    };

    issue(0, 0);
#pragma unroll
    for (int s = 0; s < 4; s++) {
        if (s + 1 < 4) {
            issue((s + 1) & 1, (s + 1) * BK);
            asm volatile("cp.async.wait_group 1;\n");
        } else {
            asm volatile("cp.async.wait_group 0;\n");
        }
        __syncthreads();
        compute(s & 1);
        __syncthreads();
    }

    // ---- epilogue: + bias, fp16 store ----
#pragma unroll
    for (int nt = 0; nt < 4; nt++) {
        const int colg = bc + wn * 32 + nt * 8 + 2 * gc;
        const float b_lo = (colg < DIMA) ? bq[colg]     : bk[colg - DIMA];
        const float b_hi = (colg < DIMA) ? bq[colg + 1] : bk[colg + 1 - DIMA];
#pragma unroll
        for (int mt = 0; mt < 2; mt++) {
            const int row0 = br + wm * 32 + mt * 16 + gr;
            const int row1 = row0 + 8;
            if (row0 < N) {
                __half2 h = __floats2half2_rn(acc[mt][nt][0] + b_lo,
                                              acc[mt][nt][1] + b_hi);
                *(__half2*)(qk + (size_t)row0 * QKDIM + colg) = h;
            }
            if (row1 < N) {
                __half2 h = __floats2half2_rn(acc[mt][nt][2] + b_lo,
                                              acc[mt][nt][3] + b_hi);
                *(__half2*)(qk + (size_t)row1 * QKDIM + colg) = h;
            }
        }
    }
}

// ---------------------------------------------------------------------------
// Edge kernel: 8 lanes per edge (4 edges per warp).
// Lane l in [0,8): loads src chunks {l, l+8, l+16, l+24} and dst chunks
// {l, l+8, l+16, l+24}; computes s[c]*d[c^16] products for c in {l, l+8,
// l+16, l+24} (i.e. q_s.k_d + k_s.q_d partials). 3-step group reduce.
// ---------------------------------------------------------------------------
__device__ __forceinline__ __half2 chunk_fma(uint4 a, uint4 b, __half2 h)
{
    const __half2* pa = (const __half2*)&a;
    const __half2* pb = (const __half2*)&b;
    h = __hfma2(pa[0], pb[0], h);
    h = __hfma2(pa[1], pb[1], h);
    h = __hfma2(pa[2], pb[2], h);
    h = __hfma2(pa[3], pb[3], h);
    return h;
}

__global__ __launch_bounds__(256)
void edge_kernel_h(const __half* __restrict__ qk,
                   const int* __restrict__ edge_index,
                   const int* __restrict__ d0_index,
                   float* __restrict__ out,   // [0:N) diagA0, [N:N+E) diagA1
                   int N, int E)
{
    const int gtid = blockIdx.x * blockDim.x + threadIdx.x;
    const int e = gtid >> 3;
    const int l = gtid & 7;
    if (e >= E) return;

    const int s = edge_index[e];
    const int d = edge_index[E + e];

    const uint4* ps = (const uint4*)(qk + (size_t)s * QKDIM);
    const uint4* pd = (const uint4*)(qk + (size_t)d * QKDIM);

    uint4 s0 = ps[l];       uint4 s1 = ps[l + 8];
    uint4 s2 = ps[l + 16];  uint4 s3 = ps[l + 24];
    uint4 d0 = pd[l];       uint4 d1 = pd[l + 8];
    uint4 d2 = pd[l + 16];  uint4 d3 = pd[l + 24];

    // q.k_d terms: s0*d2, s1*d3 ; k.q_d terms: s2*d0, s3*d1
    __half2 ha = __hmul2(((const __half2*)&s0)[0], ((const __half2*)&d2)[0]);
    {   // finish s0*d2
        const __half2* pa = (const __half2*)&s0;
        const __half2* pb = (const __half2*)&d2;
        ha = __hfma2(pa[1], pb[1], ha);
        ha = __hfma2(pa[2], pb[2], ha);
        ha = __hfma2(pa[3], pb[3], ha);
    }
    ha = chunk_fma(s1, d3, ha);
    __half2 hb = __hmul2(((const __half2*)&s2)[0], ((const __half2*)&d0)[0]);
    {
        const __half2* pa = (const __half2*)&s2;
        const __half2* pb = (const __half2*)&d0;
        hb = __hfma2(pa[1], pb[1], hb);
        hb = __hfma2(pa[2], pb[2], hb);
        hb = __hfma2(pa[3], pb[3], hb);
    }
    hb = chunk_fma(s3, d1, hb);

    float2 fa = __half22float2(ha);
    float2 fb = __half22float2(hb);
    float acc = (fa.x + fa.y) + (fb.x + fb.y);

    acc += __shfl_xor_sync(0xFFFFFFFFu, acc, 4);
    acc += __shfl_xor_sync(0xFFFFFFFFu, acc, 2);
    acc += __shfl_xor_sync(0xFFFFFFFFu, acc, 1);

    if (l < 2) {
        float val = __expf(acc * (1.0f / 16.0f));
        if (l == 0) {
            out[N + e] = val;
            atomicAdd(&out[d0_index[2 * E + 2 * e]], val);
        } else {
            atomicAdd(&out[d0_index[2 * E + 2 * e + 1]], val);
        }
    }
}

// ---------------------------------------------------------------------------
extern "C" void kernel_launch(void* const* d_in, const int* in_sizes, int n_in,
                              void* d_out, int out_size)
{
    const float* x  = (const float*)d_in[0];
    const float* Wq = (const float*)d_in[1];
    const float* bq = (const float*)d_in[2];
    const float* Wk = (const float*)d_in[3];
    const float* bk = (const float*)d_in[4];
    const int* edge_index = (const int*)d_in[5];
    const int* d0_index   = (const int*)d_in[6];
    float* out = (float*)d_out;

    const int N = in_sizes[0] / DIMD;          // 50000
    const int E = in_sizes[5] / 2;             // 800000

    __half *qk, *xh, *wh;
    cudaGetSymbolAddress((void**)&qk, g_qkh);
    cudaGetSymbolAddress((void**)&xh, g_xh);
    cudaGetSymbolAddress((void**)&wh, g_wh);

    // 0) fp32 -> fp16 converts (+ zero diagA0 region)
    {
        int n4 = (N * DIMD) / 4;
        cvt_x_kernel<<<(n4 + 255) / 256, 256>>>(x, xh, out, n4, N);
        cvt_w_kernel<<<(WROWS * DIMD / 4 + 255) / 256, 256>>>(Wq, Wk, wh);
    }
    // 1) fused q/k projection (fp16 tensor cores)
    {
        dim3 grid(WROWS / BN, (N + BM - 1) / BM);
        gemm_qk_h_kernel<<<grid, 256>>>(xh, wh, bq, bk, qk, N);
    }
    // 2) per-edge score + exp + scatter (8 lanes per edge)
    {
        long long threads_needed = (long long)E * 8;
        int blocks = (int)((threads_needed + 255) / 256);
        edge_kernel_h<<<blocks, 256>>>(qk, edge_index, d0_index, out, N, E);
    }
}

// round 8
// speedup vs baseline: 3.1943x; 1.0233x over previous
#include <cuda_runtime.h>
#include <cuda_fp16.h>
#include <cstdint>

#define MAXN 50000
#define DIMD 256      // input feature dim
#define DIMA 128      // q or k output dim
#define QKDIM 256     // q(128) + k(128) per node
#define WROWS 256     // total output features (q+k)

// device scratch
__device__ __half g_qkh[(size_t)MAXN * QKDIM];   // 25.6 MB
__device__ __half g_wh[WROWS * DIMD];            // 128 KB

// ---------------------------------------------------------------------------
// cvt_w + zero: converts W to fp16 and zeroes out[0:N).
// ---------------------------------------------------------------------------
__global__ void cvt_w_zero_kernel(const float* __restrict__ Wq,
                                  const float* __restrict__ Wk,
                                  __half* __restrict__ wh,
                                  float* __restrict__ out, int N)
{
    int i = blockIdx.x * blockDim.x + threadIdx.x;
    if (i < N) out[i] = 0.f;
    if (i < WROWS * DIMD / 4) {
        int e = i * 4;
        int row = e >> 8;           // 0..255
        int col = e & 255;
        const float* srow = (row < DIMA) ? (Wq + (size_t)row * DIMD)
                                         : (Wk + (size_t)(row - DIMA) * DIMD);
        float4 v = *(const float4*)(srow + col);
        __half2 h0 = __floats2half2_rn(v.x, v.y);
        __half2 h1 = __floats2half2_rn(v.z, v.w);
        uint2 u;
        u.x = *(const uint32_t*)&h0;
        u.y = *(const uint32_t*)&h1;
        *(uint2*)(wh + (size_t)row * DIMD + col) = u;
    }
}

// ---------------------------------------------------------------------------
// fp16 tensor-core GEMM: qk[N,256] = x(fp32,cvt inline) @ wh^T + b
// BM=64, BN=128, BK=64, 256 threads (8 warps: 2 along M x 4 along N).
// A: LDG.128 fp32 -> cvt -> swizzled STS (reg-prefetched one stage ahead).
// B: cp.async double-buffered. ldmatrix.x4 + mma.m16n8k16, fp32 accum.
// ---------------------------------------------------------------------------
#define BM 64
#define BN 128
#define BK 64

__device__ __forceinline__ void cp16(uint32_t dst, const void* src) {
    asm volatile("cp.async.cg.shared.global [%0], [%1], 16;\n"
                 :: "r"(dst), "l"(src));
}
__device__ __forceinline__ void cp_commit() {
    asm volatile("cp.async.commit_group;\n");
}
__device__ __forceinline__ void ldsm_x4(uint32_t* r, uint32_t addr) {
    asm volatile("ldmatrix.sync.aligned.m8n8.x4.shared.b16 {%0,%1,%2,%3}, [%4];"
                 : "=r"(r[0]), "=r"(r[1]), "=r"(r[2]), "=r"(r[3]) : "r"(addr));
}

__global__ __launch_bounds__(256)
void gemm_qk_h_kernel(const float* __restrict__ x, const __half* __restrict__ wh,
                      const float* __restrict__ bq, const float* __restrict__ bk,
                      __half* __restrict__ qk, int N)
{
    __shared__ __half As[2][BM * BK];   // swizzled [m][k]
    __shared__ __half Bs[2][BN * BK];   // swizzled [n][k]

    const int tid  = threadIdx.x;
    const int lane = tid & 31;
    const int wid  = tid >> 5;
    const int wm   = wid & 1;      // 2 x 32-row groups
    const int wn   = wid >> 1;     // 4 x 32-col groups
    const int gr   = lane >> 2;
    const int gc   = lane & 3;

    const int br = blockIdx.y * BM;
    const int bc = blockIdx.x * BN;    // 0,128

    const uint32_t as0 = (uint32_t)__cvta_generic_to_shared(&As[0][0]);
    const uint32_t as1 = (uint32_t)__cvta_generic_to_shared(&As[1][0]);
    const uint32_t bs0 = (uint32_t)__cvta_generic_to_shared(&Bs[0][0]);
    const uint32_t bs1 = (uint32_t)__cvta_generic_to_shared(&Bs[1][0]);

    // ldmatrix per-lane descriptors
    const int rA  = wm * 32 + (lane & 15);
    const int kcA = lane >> 4;
    const int swA = rA & 7;
    const int nB  = wn * 32 + ((lane >> 4) << 3) + (lane & 7);
    const int kcB = (lane >> 3) & 1;
    const int swB = nB & 7;

    // A staging coords: cid in [0,1024) float4s of the 64x64 tile
    // row = cid>>4 (0..63), c = cid&15 (float4 within row)
    float acc[2][4][4];
#pragma unroll
    for (int i = 0; i < 2; i++)
#pragma unroll
        for (int j = 0; j < 4; j++)
#pragma unroll
            for (int c = 0; c < 4; c++) acc[i][j][c] = 0.f;

    auto loadA = [&](float4* r, int k0) {
#pragma unroll
        for (int i = 0; i < 4; i++) {
            int cid = tid + i * 256;
            int row = cid >> 4, c = cid & 15;
            int grow = br + row; if (grow >= N) grow = N - 1;
            r[i] = *(const float4*)(x + (size_t)grow * DIMD + k0 + c * 4);
        }
    };
    auto stsA = [&](int buf, const float4* r) {
        uint32_t ab = buf ? as1 : as0;
#pragma unroll
        for (int i = 0; i < 4; i++) {
            int cid = tid + i * 256;
            int row = cid >> 4, c = cid & 15;
            __half2 h0 = __floats2half2_rn(r[i].x, r[i].y);
            __half2 h1 = __floats2half2_rn(r[i].z, r[i].w);
            uint2 u;
            u.x = *(const uint32_t*)&h0;
            u.y = *(const uint32_t*)&h1;
            int idx = row * 64 + (((c >> 1) ^ (row & 7)) << 3) + ((c & 1) << 2);
            asm volatile("st.shared.v2.b32 [%0], {%1, %2};\n"
                         :: "r"(ab + (uint32_t)idx * 2), "r"(u.x), "r"(u.y));
        }
    };
    auto issueB = [&](int buf, int k0) {
        uint32_t bb = buf ? bs1 : bs0;
#pragma unroll
        for (int i = 0; i < 4; i++) {                  // B: 1024 chunks
            int cid = tid + i * 256;
            int row = cid >> 3, c = cid & 7;
            uint32_t dst = bb + (uint32_t)(row * 64 + ((c ^ (row & 7)) << 3)) * 2;
            cp16(dst, wh + (size_t)(bc + row) * DIMD + k0 + c * 8);
        }
        cp_commit();
    };

    auto compute = [&](int buf) {
        uint32_t ab = buf ? as1 : as0;
        uint32_t bb = buf ? bs1 : bs0;
#pragma unroll
        for (int kk = 0; kk < 4; kk++) {
            uint32_t a[2][4], b[2][4];
#pragma unroll
            for (int mt = 0; mt < 2; mt++) {
                int hidx = (rA + mt * 16) * 64 + (((kk * 2 + kcA) ^ swA) << 3);
                ldsm_x4(a[mt], ab + (uint32_t)hidx * 2);
            }
#pragma unroll
            for (int np = 0; np < 2; np++) {
                int hidx = (nB + np * 16) * 64 + (((kk * 2 + kcB) ^ swB) << 3);
                ldsm_x4(b[np], bb + (uint32_t)hidx * 2);
            }
#pragma unroll
            for (int mt = 0; mt < 2; mt++)
#pragma unroll
                for (int np = 0; np < 2; np++)
#pragma unroll
                    for (int q = 0; q < 2; q++) {
                        float* c = acc[mt][np * 2 + q];
                        asm volatile(
                            "mma.sync.aligned.m16n8k16.row.col.f32.f16.f16.f32 "
                            "{%0,%1,%2,%3}, {%4,%5,%6,%7}, {%8,%9}, {%0,%1,%2,%3};\n"
                            : "+f"(c[0]), "+f"(c[1]), "+f"(c[2]), "+f"(c[3])
                            : "r"(a[mt][0]), "r"(a[mt][1]),
                              "r"(a[mt][2]), "r"(a[mt][3]),
                              "r"(b[np][q * 2]), "r"(b[np][q * 2 + 1]));
                    }
        }
    };

    float4 ra[4], rn[4];
    loadA(ra, 0);
    issueB(0, 0);
#pragma unroll
    for (int s = 0; s < 4; s++) {
        stsA(s & 1, ra);
        if (s + 1 < 4) {
            loadA(rn, (s + 1) * BK);
            issueB((s + 1) & 1, (s + 1) * BK);
            asm volatile("cp.async.wait_group 1;\n");
        } else {
            asm volatile("cp.async.wait_group 0;\n");
        }
        __syncthreads();
        compute(s & 1);
        __syncthreads();
#pragma unroll
        for (int j = 0; j < 4; j++) ra[j] = rn[j];
    }

    // ---- epilogue: + bias, fp16 store ----
#pragma unroll
    for (int nt = 0; nt < 4; nt++) {
        const int colg = bc + wn * 32 + nt * 8 + 2 * gc;
        const float b_lo = (colg < DIMA) ? bq[colg]     : bk[colg - DIMA];
        const float b_hi = (colg < DIMA) ? bq[colg + 1] : bk[colg + 1 - DIMA];
#pragma unroll
        for (int mt = 0; mt < 2; mt++) {
            const int row0 = br + wm * 32 + mt * 16 + gr;
            const int row1 = row0 + 8;
            if (row0 < N) {
                __half2 h = __floats2half2_rn(acc[mt][nt][0] + b_lo,
                                              acc[mt][nt][1] + b_hi);
                *(__half2*)(qk + (size_t)row0 * QKDIM + colg) = h;
            }
            if (row1 < N) {
                __half2 h = __floats2half2_rn(acc[mt][nt][2] + b_lo,
                                              acc[mt][nt][3] + b_hi);
                *(__half2*)(qk + (size_t)row1 * QKDIM + colg) = h;
            }
        }
    }
}

// ---------------------------------------------------------------------------
// Edge kernel: 16 lanes per edge (2 edges per warp), 4 gathers per lane.
// Lane l in [0,16): loads s chunks {l, l+16} and d chunks {l, l+16};
// partials s[l]*d[l+16] (q_s.k_d) + s[l+16]*d[l] (k_s.q_d). 4-step reduce.
// ---------------------------------------------------------------------------
__device__ __forceinline__ __half2 chunk_fma(uint4 a, uint4 b, __half2 h)
{
    const __half2* pa = (const __half2*)&a;
    const __half2* pb = (const __half2*)&b;
    h = __hfma2(pa[0], pb[0], h);
    h = __hfma2(pa[1], pb[1], h);
    h = __hfma2(pa[2], pb[2], h);
    h = __hfma2(pa[3], pb[3], h);
    return h;
}

__global__ __launch_bounds__(256)
void edge_kernel_h(const __half* __restrict__ qk,
                   const int* __restrict__ edge_index,
                   const int* __restrict__ d0_index,
                   float* __restrict__ out,   // [0:N) diagA0, [N:N+E) diagA1
                   int N, int E)
{
    const int gtid = blockIdx.x * blockDim.x + threadIdx.x;
    const int e = gtid >> 4;
    const int l = gtid & 15;
    if (e >= E) return;

    const int s = edge_index[e];
    const int d = edge_index[E + e];

    const uint4* ps = (const uint4*)(qk + (size_t)s * QKDIM);
    const uint4* pd = (const uint4*)(qk + (size_t)d * QKDIM);

    uint4 sl = ps[l];        // q_s chunk
    uint4 sh = ps[l + 16];   // k_s chunk
    uint4 dl = pd[l];        // q_d chunk
    uint4 dh = pd[l + 16];   // k_d chunk

    // prefetch scatter target (overlaps the reduce)
    int nidx = 0;
    if (l < 2) nidx = d0_index[2 * E + 2 * e + l];

    __half2 h = __hmul2(((const __half2*)&sl)[0], ((const __half2*)&dh)[0]);
    {
        const __half2* pa = (const __half2*)&sl;
        const __half2* pb = (const __half2*)&dh;
        h = __hfma2(pa[1], pb[1], h);
        h = __hfma2(pa[2], pb[2], h);
        h = __hfma2(pa[3], pb[3], h);
    }
    h = chunk_fma(sh, dl, h);

    float2 f = __half22float2(h);
    float acc = f.x + f.y;

    acc += __shfl_xor_sync(0xFFFFFFFFu, acc, 8);
    acc += __shfl_xor_sync(0xFFFFFFFFu, acc, 4);
    acc += __shfl_xor_sync(0xFFFFFFFFu, acc, 2);
    acc += __shfl_xor_sync(0xFFFFFFFFu, acc, 1);

    if (l < 2) {
        float val = __expf(acc * (1.0f / 16.0f));
        if (l == 0) out[N + e] = val;
        atomicAdd(&out[nidx], val);
    }
}

// ---------------------------------------------------------------------------
extern "C" void kernel_launch(void* const* d_in, const int* in_sizes, int n_in,
                              void* d_out, int out_size)
{
    const float* x  = (const float*)d_in[0];
    const float* Wq = (const float*)d_in[1];
    const float* bq = (const float*)d_in[2];
    const float* Wk = (const float*)d_in[3];
    const float* bk = (const float*)d_in[4];
    const int* edge_index = (const int*)d_in[5];
    const int* d0_index   = (const int*)d_in[6];
    float* out = (float*)d_out;

    const int N = in_sizes[0] / DIMD;          // 50000
    const int E = in_sizes[5] / 2;             // 800000

    __half *qk, *wh;
    cudaGetSymbolAddress((void**)&qk, g_qkh);
    cudaGetSymbolAddress((void**)&wh, g_wh);

    // 0) W fp32->fp16 + zero diagA0 region
    cvt_w_zero_kernel<<<(N + 255) / 256, 256>>>(Wq, Wk, wh, out, N);
    // 1) fused q/k projection (fp16 tensor cores, fp32 x consumed directly)
    {
        dim3 grid(WROWS / BN, (N + BM - 1) / BM);
        gemm_qk_h_kernel<<<grid, 256>>>(x, wh, bq, bk, qk, N);
    }
    // 2) per-edge score + exp + scatter (16 lanes per edge)
    {
        long long threads_needed = (long long)E * 16;
        int blocks = (int)((threads_needed + 255) / 256);
        edge_kernel_h<<<blocks, 256>>>(qk, edge_index, d0_index, out, N, E);
    }
}

// round 10
// speedup vs baseline: 3.2544x; 1.0188x over previous
#include <cuda_runtime.h>
#include <cuda_fp16.h>
#include <cstdint>

#define MAXN 50000
#define DIMD 256      // input feature dim
#define DIMA 128      // q or k output dim
#define QKDIM 256     // q(128) + k(128) per node
#define WROWS 256     // total output features (q+k)

// device scratch
__device__ __half g_qkh[(size_t)MAXN * QKDIM];   // 25.6 MB
__device__ __half g_wh[WROWS * DIMD];            // 128 KB

// ---------------------------------------------------------------------------
// cvt_w + zero: converts W to fp16 and zeroes out[0:N).
// ---------------------------------------------------------------------------
__global__ void cvt_w_zero_kernel(const float* __restrict__ Wq,
                                  const float* __restrict__ Wk,
                                  __half* __restrict__ wh,
                                  float* __restrict__ out, int N)
{
    int i = blockIdx.x * blockDim.x + threadIdx.x;
    if (i < N) out[i] = 0.f;
    if (i < WROWS * DIMD / 4) {
        int e = i * 4;
        int row = e >> 8;           // 0..255
        int col = e & 255;
        const float* srow = (row < DIMA) ? (Wq + (size_t)row * DIMD)
                                         : (Wk + (size_t)(row - DIMA) * DIMD);
        float4 v = *(const float4*)(srow + col);
        __half2 h0 = __floats2half2_rn(v.x, v.y);
        __half2 h1 = __floats2half2_rn(v.z, v.w);
        uint2 u;
        u.x = *(const uint32_t*)&h0;
        u.y = *(const uint32_t*)&h1;
        *(uint2*)(wh + (size_t)row * DIMD + col) = u;
    }
}

// ---------------------------------------------------------------------------
// fp16 tensor-core GEMM: qk[N,256] = x(fp32,cvt inline) @ wh^T + b
// BM=128, BN=256, BK=64, 512 threads (16 warps: 4 M-groups x 4 N-groups,
// warp tile 32x64). Single column pass: x read exactly once.
// A: LDG.128 fp32 -> cvt -> swizzled STS (reg-prefetched one stage ahead).
// B: cp.async double-buffered. ldmatrix.x4 + mma.m16n8k16, fp32 accum.
// Dynamic smem: As 2x16KB + Bs 2x32KB = 96KB.
// ---------------------------------------------------------------------------
#define BM 128
#define BN 256
#define BK 64
#define GEMM_SMEM (2*BM*BK*2 + 2*BN*BK*2)   // 98304 bytes

__device__ __forceinline__ void cp16(uint32_t dst, const void* src) {
    asm volatile("cp.async.cg.shared.global [%0], [%1], 16;\n"
                 :: "r"(dst), "l"(src));
}
__device__ __forceinline__ void cp_commit() {
    asm volatile("cp.async.commit_group;\n");
}
__device__ __forceinline__ void ldsm_x4(uint32_t* r, uint32_t addr) {
    asm volatile("ldmatrix.sync.aligned.m8n8.x4.shared.b16 {%0,%1,%2,%3}, [%4];"
                 : "=r"(r[0]), "=r"(r[1]), "=r"(r[2]), "=r"(r[3]) : "r"(addr));
}

__global__ __launch_bounds__(512, 1)
void gemm_qk_h_kernel(const float* __restrict__ x, const __half* __restrict__ wh,
                      const float* __restrict__ bq, const float* __restrict__ bk,
                      __half* __restrict__ qk, int N)
{
    extern __shared__ __align__(16) char smem[];

    const int tid  = threadIdx.x;
    const int lane = tid & 31;
    const int wid  = tid >> 5;
    const int wm   = wid & 3;      // 4 x 32-row groups
    const int wn   = wid >> 2;     // 4 x 64-col groups
    const int gr   = lane >> 2;
    const int gc   = lane & 3;

    const int br = blockIdx.y * BM;

    const uint32_t sbase = (uint32_t)__cvta_generic_to_shared(smem);
    const uint32_t as0 = sbase;                      // 16KB each
    const uint32_t as1 = sbase + BM * BK * 2;
    const uint32_t bs0 = sbase + 2 * BM * BK * 2;    // 32KB each
    const uint32_t bs1 = bs0 + BN * BK * 2;

    // ldmatrix per-lane descriptors
    const int rA  = wm * 32 + (lane & 15);
    const int kcA = lane >> 4;
    const int swA = rA & 7;
    const int nBb = wn * 64 + ((lane >> 4) << 3) + (lane & 7);
    const int kcB = (lane >> 3) & 1;
    const int swB = nBb & 7;

    float acc[2][8][4];
#pragma unroll
    for (int i = 0; i < 2; i++)
#pragma unroll
        for (int j = 0; j < 8; j++)
#pragma unroll
            for (int c = 0; c < 4; c++) acc[i][j][c] = 0.f;

    auto loadA = [&](float4* r, int k0) {
#pragma unroll
        for (int i = 0; i < 4; i++) {
            int cid = tid + i * 512;
            int row = cid >> 4, c = cid & 15;
            int grow = br + row; if (grow >= N) grow = N - 1;
            r[i] = *(const float4*)(x + (size_t)grow * DIMD + k0 + c * 4);
        }
    };
    auto stsA = [&](int buf, const float4* r) {
        uint32_t ab = buf ? as1 : as0;
#pragma unroll
        for (int i = 0; i < 4; i++) {
            int cid = tid + i * 512;
            int row = cid >> 4, c = cid & 15;
            __half2 h0 = __floats2half2_rn(r[i].x, r[i].y);
            __half2 h1 = __floats2half2_rn(r[i].z, r[i].w);
            uint2 u;
            u.x = *(const uint32_t*)&h0;
            u.y = *(const uint32_t*)&h1;
            int idx = row * 64 + (((c >> 1) ^ (row & 7)) << 3) + ((c & 1) << 2);
            asm volatile("st.shared.v2.b32 [%0], {%1, %2};\n"
                         :: "r"(ab + (uint32_t)idx * 2), "r"(u.x), "r"(u.y));
        }
    };
    auto issueB = [&](int buf, int k0) {
        uint32_t bb = buf ? bs1 : bs0;
#pragma unroll
        for (int i = 0; i < 4; i++) {                  // B: 2048 chunks / 512 thr
            int cid = tid + i * 512;
            int row = cid >> 3, c = cid & 7;
            uint32_t dst = bb + (uint32_t)(row * 64 + ((c ^ (row & 7)) << 3)) * 2;
            cp16(dst, wh + (size_t)row * DIMD + k0 + c * 8);
        }
        cp_commit();
    };

    auto compute = [&](int buf) {
        uint32_t ab = buf ? as1 : as0;
        uint32_t bb = buf ? bs1 : bs0;
#pragma unroll
        for (int kk = 0; kk < 4; kk++) {
            uint32_t a[2][4], b[4][4];
#pragma unroll
            for (int mt = 0; mt < 2; mt++) {
                int hidx = (rA + mt * 16) * 64 + (((kk * 2 + kcA) ^ swA) << 3);
                ldsm_x4(a[mt], ab + (uint32_t)hidx * 2);
            }
#pragma unroll
            for (int np = 0; np < 4; np++) {
                int hidx = (nBb + np * 16) * 64 + (((kk * 2 + kcB) ^ swB) << 3);
                ldsm_x4(b[np], bb + (uint32_t)hidx * 2);
            }
#pragma unroll
            for (int mt = 0; mt < 2; mt++)
#pragma unroll
                for (int np = 0; np < 4; np++)
#pragma unroll
                    for (int q = 0; q < 2; q++) {
                        float* c = acc[mt][np * 2 + q];
                        asm volatile(
                            "mma.sync.aligned.m16n8k16.row.col.f32.f16.f16.f32 "
                            "{%0,%1,%2,%3}, {%4,%5,%6,%7}, {%8,%9}, {%0,%1,%2,%3};\n"
                            : "+f"(c[0]), "+f"(c[1]), "+f"(c[2]), "+f"(c[3])
                            : "r"(a[mt][0]), "r"(a[mt][1]),
                              "r"(a[mt][2]), "r"(a[mt][3]),
                              "r"(b[np][q * 2]), "r"(b[np][q * 2 + 1]));
                    }
        }
    };

    float4 ra[4], rn[4];
    loadA(ra, 0);
    issueB(0, 0);
#pragma unroll
    for (int s = 0; s < 4; s++) {
        stsA(s & 1, ra);
        if (s + 1 < 4) {
            loadA(rn, (s + 1) * BK);
            issueB((s + 1) & 1, (s + 1) * BK);
            asm volatile("cp.async.wait_group 1;\n");
        } else {
            asm volatile("cp.async.wait_group 0;\n");
        }
        __syncthreads();
        compute(s & 1);
        __syncthreads();
#pragma unroll
        for (int j = 0; j < 4; j++) ra[j] = rn[j];
    }

    // ---- epilogue: + bias, fp16 store ----
#pragma unroll
    for (int np = 0; np < 4; np++)
#pragma unroll
    for (int q = 0; q < 2; q++) {
        const int colg = wn * 64 + np * 16 + q * 8 + 2 * gc;
        const float b_lo = (colg < DIMA) ? bq[colg]     : bk[colg - DIMA];
        const float b_hi = (colg < DIMA) ? bq[colg + 1] : bk[colg + 1 - DIMA];
#pragma unroll
        for (int mt = 0; mt < 2; mt++) {
            const int row0 = br + wm * 32 + mt * 16 + gr;
            const int row1 = row0 + 8;
            float* c = acc[mt][np * 2 + q];
            if (row0 < N) {
                __half2 h = __floats2half2_rn(c[0] + b_lo, c[1] + b_hi);
                *(__half2*)(qk + (size_t)row0 * QKDIM + colg) = h;
            }
            if (row1 < N) {
                __half2 h = __floats2half2_rn(c[2] + b_lo, c[3] + b_hi);
                *(__half2*)(qk + (size_t)row1 * QKDIM + colg) = h;
            }
        }
    }
}

// ---------------------------------------------------------------------------
// Edge kernel: 16 lanes per edge (2 edges per warp), 4 gathers per lane.
// (At the LTS chip cap — do not touch without cutting bytes.)
// ---------------------------------------------------------------------------
__device__ __forceinline__ __half2 chunk_fma(uint4 a, uint4 b, __half2 h)
{
    const __half2* pa = (const __half2*)&a;
    const __half2* pb = (const __half2*)&b;
    h = __hfma2(pa[0], pb[0], h);
    h = __hfma2(pa[1], pb[1], h);
    h = __hfma2(pa[2], pb[2], h);
    h = __hfma2(pa[3], pb[3], h);
    return h;
}

__global__ __launch_bounds__(256)
void edge_kernel_h(const __half* __restrict__ qk,
                   const int* __restrict__ edge_index,
                   const int* __restrict__ d0_index,
                   float* __restrict__ out,   // [0:N) diagA0, [N:N+E) diagA1
                   int N, int E)
{
    const int gtid = blockIdx.x * blockDim.x + threadIdx.x;
    const int e = gtid >> 4;
    const int l = gtid & 15;
    if (e >= E) return;

    const int s = edge_index[e];
    const int d = edge_index[E + e];

    const uint4* ps = (const uint4*)(qk + (size_t)s * QKDIM);
    const uint4* pd = (const uint4*)(qk + (size_t)d * QKDIM);

    uint4 sl = ps[l];        // q_s chunk
    uint4 sh = ps[l + 16];   // k_s chunk
    uint4 dl = pd[l];        // q_d chunk
    uint4 dh = pd[l + 16];   // k_d chunk

    // prefetch scatter target (overlaps the reduce)
    int nidx = 0;
    if (l < 2) nidx = d0_index[2 * E + 2 * e + l];

    __half2 h = __hmul2(((const __half2*)&sl)[0], ((const __half2*)&dh)[0]);
    {
        const __half2* pa = (const __half2*)&sl;
        const __half2* pb = (const __half2*)&dh;
        h = __hfma2(pa[1], pb[1], h);
        h = __hfma2(pa[2], pb[2], h);
        h = __hfma2(pa[3], pb[3], h);
    }
    h = chunk_fma(sh, dl, h);

    float2 f = __half22float2(h);
    float acc = f.x + f.y;

    acc += __shfl_xor_sync(0xFFFFFFFFu, acc, 8);
    acc += __shfl_xor_sync(0xFFFFFFFFu, acc, 4);
    acc += __shfl_xor_sync(0xFFFFFFFFu, acc, 2);
    acc += __shfl_xor_sync(0xFFFFFFFFu, acc, 1);

    if (l < 2) {
        float val = __expf(acc * (1.0f / 16.0f));
        if (l == 0) out[N + e] = val;
        atomicAdd(&out[nidx], val);
    }
}

// ---------------------------------------------------------------------------
extern "C" void kernel_launch(void* const* d_in, const int* in_sizes, int n_in,
                              void* d_out, int out_size)
{
    const float* x  = (const float*)d_in[0];
    const float* Wq = (const float*)d_in[1];
    const float* bq = (const float*)d_in[2];
    const float* Wk = (const float*)d_in[3];
    const float* bk = (const float*)d_in[4];
    const int* edge_index = (const int*)d_in[5];
    const int* d0_index   = (const int*)d_in[6];
    float* out = (float*)d_out;

    const int N = in_sizes[0] / DIMD;          // 50000
    const int E = in_sizes[5] / 2;             // 800000

    __half *qk, *wh;
    cudaGetSymbolAddress((void**)&qk, g_qkh);
    cudaGetSymbolAddress((void**)&wh, g_wh);

    // 0) W fp32->fp16 + zero diagA0 region
    cvt_w_zero_kernel<<<(N + 255) / 256, 256>>>(Wq, Wk, wh, out, N);
    // 1) fused q/k projection (fp16 tensor cores, single column pass)
    {
        cudaFuncSetAttribute(gemm_qk_h_kernel,
                             cudaFuncAttributeMaxDynamicSharedMemorySize,
                             GEMM_SMEM);
        dim3 grid(1, (N + BM - 1) / BM);
        gemm_qk_h_kernel<<<grid, 512, GEMM_SMEM>>>(x, wh, bq, bk, qk, N);
    }
    // 2) per-edge score + exp + scatter (16 lanes per edge)
    {
        long long threads_needed = (long long)E * 16;
        int blocks = (int)((threads_needed + 255) / 256);
        edge_kernel_h<<<blocks, 256>>>(qk, edge_index, d0_index, out, N, E);
    }
}

// round 14
// speedup vs baseline: 3.3336x; 1.0243x over previous
#include <cuda_runtime.h>
#include <cuda_fp16.h>
#include <cstdint>

#define MAXN 50000
#define DIMD 256      // input feature dim
#define DIMA 128      // q or k output dim
#define QKDIM 256     // q(128) + k(128) per node
#define WROWS 256     // total output features (q+k)

// device scratch
__device__ __half g_qkh[(size_t)MAXN * QKDIM];   // 25.6 MB
__device__ __half g_wh[WROWS * DIMD];            // 128 KB

// ---------------------------------------------------------------------------
// cvt_w + zero: converts W to fp16 and zeroes out[0:N).
// ---------------------------------------------------------------------------
__global__ void cvt_w_zero_kernel(const float* __restrict__ Wq,
                                  const float* __restrict__ Wk,
                                  __half* __restrict__ wh,
                                  float* __restrict__ out, int N)
{
    int i = blockIdx.x * blockDim.x + threadIdx.x;
    if (i < N) out[i] = 0.f;
    if (i < WROWS * DIMD / 4) {
        int e = i * 4;
        int row = e >> 8;           // 0..255
        int col = e & 255;
        const float* srow = (row < DIMA) ? (Wq + (size_t)row * DIMD)
                                         : (Wk + (size_t)(row - DIMA) * DIMD);
        float4 v = *(const float4*)(srow + col);
        __half2 h0 = __floats2half2_rn(v.x, v.y);
        __half2 h1 = __floats2half2_rn(v.z, v.w);
        uint2 u;
        u.x = *(const uint32_t*)&h0;
        u.y = *(const uint32_t*)&h1;
        *(uint2*)(wh + (size_t)row * DIMD + col) = u;
    }
}

// ---------------------------------------------------------------------------
// fp16 tensor-core GEMM: qk[N,256] = x(fp32,cvt inline) @ wh^T + b
// BM=64, BN=256, BK=64, 256 threads (8 warps: 2 M-groups x 4 N-groups,
// warp tile 32x64). Single column pass (x read once); 2 blocks/SM for
// latency overlap. smem 80KB dynamic.
// ---------------------------------------------------------------------------
#define BM 64
#define BN 256
#define BK 64
#define GEMM_SMEM (2*BM*BK*2 + 2*BN*BK*2)   // 81920 bytes

__device__ __forceinline__ void cp16(uint32_t dst, const void* src) {
    asm volatile("cp.async.cg.shared.global [%0], [%1], 16;\n"
                 :: "r"(dst), "l"(src));
}
__device__ __forceinline__ void cp_commit() {
    asm volatile("cp.async.commit_group;\n");
}
__device__ __forceinline__ void ldsm_x4(uint32_t* r, uint32_t addr) {
    asm volatile("ldmatrix.sync.aligned.m8n8.x4.shared.b16 {%0,%1,%2,%3}, [%4];"
                 : "=r"(r[0]), "=r"(r[1]), "=r"(r[2]), "=r"(r[3]) : "r"(addr));
}

__global__ __launch_bounds__(256, 2)
void gemm_qk_h_kernel(const float* __restrict__ x, const __half* __restrict__ wh,
                      const float* __restrict__ bq, const float* __restrict__ bk,
                      __half* __restrict__ qk, int N)
{
    extern __shared__ __align__(16) char smem[];

    const int tid  = threadIdx.x;
    const int lane = tid & 31;
    const int wid  = tid >> 5;
    const int wm   = wid & 1;      // 2 x 32-row groups
    const int wn   = wid >> 1;     // 4 x 64-col groups
    const int gr   = lane >> 2;
    const int gc   = lane & 3;

    const int br = blockIdx.y * BM;

    const uint32_t sbase = (uint32_t)__cvta_generic_to_shared(smem);
    const uint32_t as0 = sbase;                      // 8KB each
    const uint32_t as1 = sbase + BM * BK * 2;
    const uint32_t bs0 = sbase + 2 * BM * BK * 2;    // 32KB each
    const uint32_t bs1 = bs0 + BN * BK * 2;

    // ldmatrix per-lane descriptors
    const int rA  = wm * 32 + (lane & 15);
    const int kcA = lane >> 4;
    const int swA = rA & 7;
    const int nBb = wn * 64 + ((lane >> 4) << 3) + (lane & 7);
    const int kcB = (lane >> 3) & 1;
    const int swB = nBb & 7;

    float acc[2][8][4];
#pragma unroll
    for (int i = 0; i < 2; i++)
#pragma unroll
        for (int j = 0; j < 8; j++)
#pragma unroll
            for (int c = 0; c < 4; c++) acc[i][j][c] = 0.f;

    auto loadA = [&](float4* r, int k0) {
#pragma unroll
        for (int i = 0; i < 4; i++) {
            int cid = tid + i * 256;
            int row = cid >> 4, c = cid & 15;
            int grow = br + row; if (grow >= N) grow = N - 1;
            r[i] = *(const float4*)(x + (size_t)grow * DIMD + k0 + c * 4);
        }
    };
    auto stsA = [&](int buf, const float4* r) {
        uint32_t ab = buf ? as1 : as0;
#pragma unroll
        for (int i = 0; i < 4; i++) {
            int cid = tid + i * 256;
            int row = cid >> 4, c = cid & 15;
            __half2 h0 = __floats2half2_rn(r[i].x, r[i].y);
            __half2 h1 = __floats2half2_rn(r[i].z, r[i].w);
            uint2 u;
            u.x = *(const uint32_t*)&h0;
            u.y = *(const uint32_t*)&h1;
            int idx = row * 64 + (((c >> 1) ^ (row & 7)) << 3) + ((c & 1) << 2);
            asm volatile("st.shared.v2.b32 [%0], {%1, %2};\n"
                         :: "r"(ab + (uint32_t)idx * 2), "r"(u.x), "r"(u.y));
        }
    };
    auto issueB = [&](int buf, int k0) {
        uint32_t bb = buf ? bs1 : bs0;
#pragma unroll
        for (int i = 0; i < 8; i++) {                  // B: 2048 chunks / 256 thr
            int cid = tid + i * 256;
            int row = cid >> 3, c = cid & 7;
            uint32_t dst = bb + (uint32_t)(row * 64 + ((c ^ (row & 7)) << 3)) * 2;
            cp16(dst, wh + (size_t)row * DIMD + k0 + c * 8);
        }
        cp_commit();
    };

    auto compute = [&](int buf) {
        uint32_t ab = buf ? as1 : as0;
        uint32_t bb = buf ? bs1 : bs0;
#pragma unroll
        for (int kk = 0; kk < 4; kk++) {
            uint32_t a[2][4], b[4][4];
#pragma unroll
            for (int mt = 0; mt < 2; mt++) {
                int hidx = (rA + mt * 16) * 64 + (((kk * 2 + kcA) ^ swA) << 3);
                ldsm_x4(a[mt], ab + (uint32_t)hidx * 2);
            }
#pragma unroll
            for (int np = 0; np < 4; np++) {
                int hidx = (nBb + np * 16) * 64 + (((kk * 2 + kcB) ^ swB) << 3);
                ldsm_x4(b[np], bb + (uint32_t)hidx * 2);
            }
#pragma unroll
            for (int mt = 0; mt < 2; mt++)
#pragma unroll
                for (int np = 0; np < 4; np++)
#pragma unroll
                    for (int q = 0; q < 2; q++) {
                        float* c = acc[mt][np * 2 + q];
                        asm volatile(
                            "mma.sync.aligned.m16n8k16.row.col.f32.f16.f16.f32 "
                            "{%0,%1,%2,%3}, {%4,%5,%6,%7}, {%8,%9}, {%0,%1,%2,%3};\n"
                            : "+f"(c[0]), "+f"(c[1]), "+f"(c[2]), "+f"(c[3])
                            : "r"(a[mt][0]), "r"(a[mt][1]),
                              "r"(a[mt][2]), "r"(a[mt][3]),
                              "r"(b[np][q * 2]), "r"(b[np][q * 2 + 1]));
                    }
        }
    };

    float4 ra[4], rn[4];
    loadA(ra, 0);
    issueB(0, 0);
#pragma unroll
    for (int s = 0; s < 4; s++) {
        stsA(s & 1, ra);
        if (s + 1 < 4) {
            loadA(rn, (s + 1) * BK);
            issueB((s + 1) & 1, (s + 1) * BK);
            asm volatile("cp.async.wait_group 1;\n");
        } else {
            asm volatile("cp.async.wait_group 0;\n");
        }
        __syncthreads();
        compute(s & 1);
        __syncthreads();
#pragma unroll
        for (int j = 0; j < 4; j++) ra[j] = rn[j];
    }

    // ---- epilogue: + bias, fp16 store ----
#pragma unroll
    for (int np = 0; np < 4; np++)
#pragma unroll
    for (int q = 0; q < 2; q++) {
        const int colg = wn * 64 + np * 16 + q * 8 + 2 * gc;
        const float b_lo = (colg < DIMA) ? bq[colg]     : bk[colg - DIMA];
        const float b_hi = (colg < DIMA) ? bq[colg + 1] : bk[colg + 1 - DIMA];
#pragma unroll
        for (int mt = 0; mt < 2; mt++) {
            const int row0 = br + wm * 32 + mt * 16 + gr;
            const int row1 = row0 + 8;
            float* c = acc[mt][np * 2 + q];
            if (row0 < N) {
                __half2 h = __floats2half2_rn(c[0] + b_lo, c[1] + b_hi);
                *(__half2*)(qk + (size_t)row0 * QKDIM + colg) = h;
            }
            if (row1 < N) {
                __half2 h = __floats2half2_rn(c[2] + b_lo, c[3] + b_hi);
                *(__half2*)(qk + (size_t)row1 * QKDIM + colg) = h;
            }
        }
    }
}

// ---------------------------------------------------------------------------
// Edge kernel: 16 lanes per edge (2 edges per warp), 4 gathers per lane.
// (At the LTS byte floor — do not touch without cutting bytes.)
// ---------------------------------------------------------------------------
__device__ __forceinline__ __half2 chunk_fma(uint4 a, uint4 b, __half2 h)
{
    const __half2* pa = (const __half2*)&a;
    const __half2* pb = (const __half2*)&b;
    h = __hfma2(pa[0], pb[0], h);
    h = __hfma2(pa[1], pb[1], h);
    h = __hfma2(pa[2], pb[2], h);
    h = __hfma2(pa[3], pb[3], h);
    return h;
}

__global__ __launch_bounds__(256)
void edge_kernel_h(const __half* __restrict__ qk,
                   const int* __restrict__ edge_index,
                   const int* __restrict__ d0_index,
                   float* __restrict__ out,   // [0:N) diagA0, [N:N+E) diagA1
                   int N, int E)
{
    const int gtid = blockIdx.x * blockDim.x + threadIdx.x;
    const int e = gtid >> 4;
    const int l = gtid & 15;
    if (e >= E) return;

    const int s = edge_index[e];
    const int d = edge_index[E + e];

    const uint4* ps = (const uint4*)(qk + (size_t)s * QKDIM);
    const uint4* pd = (const uint4*)(qk + (size_t)d * QKDIM);

    uint4 sl = ps[l];        // q_s chunk
    uint4 sh = ps[l + 16];   // k_s chunk
    uint4 dl = pd[l];        // q_d chunk
    uint4 dh = pd[l + 16];   // k_d chunk

    // prefetch scatter target (overlaps the reduce)
    int nidx = 0;
    if (l < 2) nidx = d0_index[2 * E + 2 * e + l];

    __half2 h = __hmul2(((const __half2*)&sl)[0], ((const __half2*)&dh)[0]);
    {
        const __half2* pa = (const __half2*)&sl;
        const __half2* pb = (const __half2*)&dh;
        h = __hfma2(pa[1], pb[1], h);
        h = __hfma2(pa[2], pb[2], h);
        h = __hfma2(pa[3], pb[3], h);
    }
    h = chunk_fma(sh, dl, h);

    float2 f = __half22float2(h);
    float acc = f.x + f.y;

    acc += __shfl_xor_sync(0xFFFFFFFFu, acc, 8);
    acc += __shfl_xor_sync(0xFFFFFFFFu, acc, 4);
    acc += __shfl_xor_sync(0xFFFFFFFFu, acc, 2);
    acc += __shfl_xor_sync(0xFFFFFFFFu, acc, 1);

    if (l < 2) {
        float val = __expf(acc * (1.0f / 16.0f));
        if (l == 0) out[N + e] = val;
        atomicAdd(&out[nidx], val);
    }
}

// ---------------------------------------------------------------------------
extern "C" void kernel_launch(void* const* d_in, const int* in_sizes, int n_in,
                              void* d_out, int out_size)
{
    const float* x  = (const float*)d_in[0];
    const float* Wq = (const float*)d_in[1];
    const float* bq = (const float*)d_in[2];
    const float* Wk = (const float*)d_in[3];
    const float* bk = (const float*)d_in[4];
    const int* edge_index = (const int*)d_in[5];
    const int* d0_index   = (const int*)d_in[6];
    float* out = (float*)d_out;

    const int N = in_sizes[0] / DIMD;          // 50000
    const int E = in_sizes[5] / 2;             // 800000

    __half *qk, *wh;
    cudaGetSymbolAddress((void**)&qk, g_qkh);
    cudaGetSymbolAddress((void**)&wh, g_wh);

    // 0) W fp32->fp16 + zero diagA0 region
    cvt_w_zero_kernel<<<(N + 255) / 256, 256>>>(Wq, Wk, wh, out, N);
    // 1) fused q/k projection (fp16 tensor cores, single column pass, 2 CTA/SM)
    {
        cudaFuncSetAttribute(gemm_qk_h_kernel,
                             cudaFuncAttributeMaxDynamicSharedMemorySize,
                             GEMM_SMEM);
        dim3 grid(1, (N + BM - 1) / BM);
        gemm_qk_h_kernel<<<grid, 256, GEMM_SMEM>>>(x, wh, bq, bk, qk, N);
    }
    // 2) per-edge score + exp + scatter (16 lanes per edge)
    {
        long long threads_needed = (long long)E * 16;
        int blocks = (int)((threads_needed + 255) / 256);
        edge_kernel_h<<<blocks, 256>>>(qk, edge_index, d0_index, out, N, E);
    }
}